// round 5
// baseline (speedup 1.0000x reference)
#include <cuda_runtime.h>
#include <math.h>

namespace {
constexpr int kB = 32, kC = 192, kH = 56, kW = 56;
constexpr int kHeads = 6, kD = 32, kWS = 7, kShift = 3, kHid = 768;
constexpr int kNWin = kB * 8 * 8;
constexpr int kTok = kWS * kWS;
constexpr int kNT = kNWin * kTok;
constexpr int kHWp = kH * kW;
}

// ---------------- scratch ----------------------------------------------------
__device__ float g_wt1[kC * 9 * kHid];          // conv1 w transposed, tf32-rounded
__device__ float g_wt2[kHid * 9 * kC];
__device__ float g_wqr[3 * kC * kC];            // qkv w, tf32-rounded
__device__ float g_wpr[kC * kC];                // proj w, tf32-rounded
__device__ float g_xw[(size_t)kNT * kC];        // LN1 out (rounded), [win][tok][c]
__device__ float g_q [(size_t)kNT * kC];
__device__ float g_kk[(size_t)kNT * kC];
__device__ float g_vv[(size_t)kNT * kC];
__device__ float g_ao[(size_t)kNT * kC];        // attn out (rounded), [win][tok][c]
__device__ float g_x1[(size_t)kNT * kC];        // x + attn branch (NCHW)
__device__ float g_h0[(size_t)kNT * kC];        // LN2 out (NCHW), rounded
__device__ float g_h1[(size_t)kNT * kHid];      // conv1+gelu out (NCHW), rounded

// ---------------- helpers ----------------------------------------------------
__device__ __forceinline__ unsigned f2tf32(float x) {
    unsigned r; asm("cvt.rna.tf32.f32 %0, %1;" : "=r"(r) : "f"(x)); return r;
}
__device__ __forceinline__ void mma_tf32(float* d, const unsigned* a, const unsigned* b) {
    asm volatile(
        "mma.sync.aligned.m16n8k8.row.col.f32.tf32.tf32.f32 "
        "{%0,%1,%2,%3}, {%4,%5,%6,%7}, {%8,%9}, {%0,%1,%2,%3};\n"
        : "+f"(d[0]), "+f"(d[1]), "+f"(d[2]), "+f"(d[3])
        : "r"(a[0]), "r"(a[1]), "r"(a[2]), "r"(a[3]), "r"(b[0]), "r"(b[1]));
}
__device__ __forceinline__ void cp4(unsigned dst, const void* src, int sz) {
    asm volatile("cp.async.ca.shared.global [%0], [%1], 4, %2;" :: "r"(dst), "l"(src), "r"(sz));
}
__device__ __forceinline__ void cp16(unsigned dst, const void* src) {
    asm volatile("cp.async.cg.shared.global [%0], [%1], 16;" :: "r"(dst), "l"(src));
}
__device__ __forceinline__ void cp_commit() { asm volatile("cp.async.commit_group;"); }
__device__ __forceinline__ void cp_wait2()  { asm volatile("cp.async.wait_group 2;"); }

// ---------------- weight prep ------------------------------------------------
template<int PH>
__global__ void wtrans_kernel(const float* __restrict__ w) {
    constexpr int OC = (PH == 0) ? kHid : kC;
    constexpr int IC = (PH == 0) ? kC : kHid;
    float* wt = (PH == 0) ? g_wt1 : g_wt2;
    int i = blockIdx.x * 256 + threadIdx.x;
    if (i < OC * IC * 9) {
        int o = i / (IC * 9);
        int ct = i - o * (IC * 9);
        wt[(size_t)ct * OC + o] = __uint_as_float(f2tf32(w[i]));
    }
}
template<int P>
__global__ void wround_kernel(const float* __restrict__ w) {
    constexpr int N = (P == 0) ? 3 * kC * kC : kC * kC;
    float* dst = (P == 0) ? g_wqr : g_wpr;
    int i = blockIdx.x * 256 + threadIdx.x;
    if (i < N) dst[i] = __uint_as_float(f2tf32(w[i]));
}

// ---------------- LayerNorm --------------------------------------------------
template<int MODE>
__global__ void ln_kernel(const float* __restrict__ xin,
                          const float* __restrict__ gam,
                          const float* __restrict__ bet) {
    int p = blockIdx.x * 256 + threadIdx.x;
    if (p >= kNT) return;
    const float* src = (MODE == 0) ? xin : g_x1;
    int b = p / kHWp;
    int rem = p - b * kHWp;
    int hp = rem / kW, wp = rem - (rem / kW) * kW;
    int h = hp, w = wp;
    if (MODE == 0) {
        h = hp + kShift; if (h >= kH) h -= kH;
        w = wp + kShift; if (w >= kW) w -= kW;
    }
    const float* xp = src + ((size_t)b * kC) * kHWp + h * kW + w;
    float s = 0.f, s2 = 0.f;
#pragma unroll 4
    for (int c = 0; c < kC; c++) { float v = xp[(size_t)c * kHWp]; s += v; s2 += v * v; }
    float m = s * (1.f / kC);
    float var = s2 * (1.f / kC) - m * m;
    float rs = rsqrtf(var + 1e-5f);
    if (MODE == 0) {
        int win = b * 64 + (hp / 7) * 8 + (wp / 7);
        int tok = (hp % 7) * 7 + (wp % 7);
        float* op = g_xw + ((size_t)win * kTok + tok) * kC;
#pragma unroll 4
        for (int c = 0; c < kC; c++) {
            float v = (xp[(size_t)c * kHWp] - m) * rs * gam[c] + bet[c];
            op[c] = __uint_as_float(f2tf32(v));
        }
    } else {
        float* op = g_h0 + ((size_t)b * kC) * kHWp + h * kW + w;
#pragma unroll 4
        for (int c = 0; c < kC; c++) {
            float v = (xp[(size_t)c * kHWp] - m) * rs * gam[c] + bet[c];
            op[(size_t)c * kHWp] = __uint_as_float(f2tf32(v));
        }
    }
}

// ---------------- GEMM via tf32 MMA, cp.async 3-deep pipeline ----------------
// 128 thr, block tile 256 tok x 64 out, warp = 64 tok x 64 out, k-chunk 16.
// smem per buffer: sA[256][20] + sW[64][20] = 6400 words.
template<int EPI>
__global__ __launch_bounds__(128, 2) void gemm_mma_kernel(const float* __restrict__ bias,
                                                          const float* __restrict__ xin) {
    extern __shared__ unsigned gsm[];
    const float* A  = (EPI == 0) ? g_xw : g_ao;
    const float* Wr = (EPI == 0) ? g_wqr : g_wpr;
    const int tid = threadIdx.x;
    const int warp = tid >> 5, lane = tid & 31;
    const int g = lane >> 2, t = lane & 3;
    const int wm = warp;
    const int tokbase = blockIdx.x * 256;
    const int ob = blockIdx.y * 64;
    const unsigned smem0 = (unsigned)__cvta_generic_to_shared(gsm);

    // hoisted staging addresses
    const int arow = tid >> 2, aq = (tid & 3) << 2;      // +32 rows per step, 8 steps
    const float* Asrc = A + (size_t)(tokbase + arow) * kC + aq;
    const float* Wsrc = Wr + (size_t)(ob + arow) * kC + aq;

    auto stage = [&](int kc, int bufi) {
        const unsigned base = smem0 + (unsigned)(bufi * 6400 * 4);
        const float* ap = Asrc + kc * 16;
#pragma unroll
        for (int r = 0; r < 8; r++)
            cp16(base + (unsigned)(((arow + r * 32) * 20 + aq) << 2), ap + (size_t)(r * 32) * kC);
        const float* wpp = Wsrc + kc * 16;
#pragma unroll
        for (int r = 0; r < 2; r++)
            cp16(base + (unsigned)((5120 + (arow + r * 32) * 20 + aq) << 2), wpp + (size_t)(r * 32) * kC);
    };

    float acc[4][8][4];
#pragma unroll
    for (int i = 0; i < 4; i++)
#pragma unroll
        for (int j = 0; j < 8; j++)
#pragma unroll
            for (int k = 0; k < 4; k++) acc[i][j][k] = 0.f;

    stage(0, 0); cp_commit();
    stage(1, 1); cp_commit();

    constexpr int NK = kC / 16;   // 12
    for (int kc = 0; kc < NK; kc++) {
        if (kc + 2 < NK) stage(kc + 2, (kc + 2) % 3);
        cp_commit();
        cp_wait2();
        __syncthreads();
        const unsigned* buf = gsm + (kc % 3) * 6400;
#pragma unroll
        for (int s = 0; s < 2; s++) {
            unsigned afr[4][4];
#pragma unroll
            for (int mf = 0; mf < 4; mf++) {
                const int mrow = wm * 64 + mf * 16 + g;
                afr[mf][0] = buf[mrow * 20 + s * 8 + t];
                afr[mf][1] = buf[(mrow + 8) * 20 + s * 8 + t];
                afr[mf][2] = buf[mrow * 20 + s * 8 + t + 4];
                afr[mf][3] = buf[(mrow + 8) * 20 + s * 8 + t + 4];
            }
            unsigned bfr[8][2];
#pragma unroll
            for (int nf = 0; nf < 8; nf++) {
                const int n = nf * 8 + g;
                bfr[nf][0] = buf[5120 + n * 20 + s * 8 + t];
                bfr[nf][1] = buf[5120 + n * 20 + s * 8 + t + 4];
            }
#pragma unroll
            for (int mf = 0; mf < 4; mf++)
#pragma unroll
                for (int nf = 0; nf < 8; nf++)
                    mma_tf32(acc[mf][nf], afr[mf], bfr[nf]);
        }
        __syncthreads();
    }

#pragma unroll
    for (int mf = 0; mf < 4; mf++) {
        const int tk0 = tokbase + wm * 64 + mf * 16 + g;
#pragma unroll
        for (int nf = 0; nf < 8; nf++) {
            const int o0 = ob + nf * 8 + 2 * t;
            const float bv0 = bias[o0], bv1 = bias[o0 + 1];
            float vals[4] = {acc[mf][nf][0] + bv0, acc[mf][nf][1] + bv1,
                             acc[mf][nf][2] + bv0, acc[mf][nf][3] + bv1};
#pragma unroll
            for (int q = 0; q < 4; q++) {
                const int n_tok = tk0 + (q >> 1) * 8;
                const int mo = o0 + (q & 1);
                const int win = n_tok / 49, tok = n_tok - win * 49;
                if (EPI == 0) {
                    int sec = mo / kC;
                    int c = mo - sec * kC;
                    float* dst = (sec == 0) ? g_q : (sec == 1) ? g_kk : g_vv;
                    dst[((size_t)(win * kHeads + (c >> 5)) * kTok + tok) * kD + (c & 31)] = vals[q];
                } else {
                    int bb  = win >> 6;
                    int whh = (win >> 3) & 7;
                    int www = win & 7;
                    int ti = tok / 7, tj = tok - ti * 7;
                    int hi = whh * 7 + ti + kShift; if (hi >= kH) hi -= kH;
                    int wi = www * 7 + tj + kShift; if (wi >= kW) wi -= kW;
                    size_t idx = ((size_t)(bb * kC + mo) * kH + hi) * kW + wi;
                    g_x1[idx] = xin[idx] + vals[q];
                }
            }
        }
    }
}

// ---------------- attention --------------------------------------------------
__global__ __launch_bounds__(64) void attn_kernel() {
    const int wh = blockIdx.x;
    __shared__ float sq[kTok * 33], sk[kTok * kD], sv[kTok * kD];
    const size_t base = (size_t)wh * kTok * kD;
    for (int i = threadIdx.x; i < kTok * kD; i += 64) {
        int r = i >> 5, d = i & 31;
        sq[r * 33 + d] = g_q[base + i];
        sk[i] = g_kk[base + i];
        sv[i] = g_vv[base + i];
    }
    __syncthreads();
    const int r = threadIdx.x;
    if (r < kTok) {
        float qr[kD];
#pragma unroll
        for (int d = 0; d < kD; d++) qr[d] = sq[r * 33 + d];
        float p[kTok];
        float mx = -1e30f;
#pragma unroll
        for (int m = 0; m < kTok; m++) {
            float dot = 0.f;
#pragma unroll
            for (int d = 0; d < kD; d++) dot += qr[d] * sk[m * kD + d];
            dot *= 0.17677669529663689f;
            p[m] = dot;
            mx = fmaxf(mx, dot);
        }
        float sum = 0.f;
#pragma unroll
        for (int m = 0; m < kTok; m++) { p[m] = __expf(p[m] - mx); sum += p[m]; }
        const float inv = 1.f / sum;
        const int win = wh / kHeads, head = wh - win * kHeads;
        float* op = g_ao + ((size_t)win * kTok + r) * kC + head * kD;
#pragma unroll 4
        for (int d = 0; d < kD; d++) {
            float a = 0.f;
#pragma unroll
            for (int m = 0; m < kTok; m++) a += p[m] * sv[m * kD + d];
            op[d] = __uint_as_float(f2tf32(a * inv));
        }
    }
}

// ---------------- 3x3 conv via tf32 MMA, 3-deep cp.async pipeline ------------
// 128 thr / 4 warps, tile 8 rows x 32 cols (256 px) x 64 oc.
// smem per buffer: sx 8*10*36 = 2880 w + sw 72*72 = 5184 w = 8064 words.
template<int PH>
__global__ __launch_bounds__(128, 2) void conv3x3_mma_kernel(const float* __restrict__ bias,
                                                             float* __restrict__ outp) {
    constexpr int IC = (PH == 0) ? kC : kHid;
    constexpr int OC = (PH == 0) ? kHid : kC;
    constexpr int NCH = IC / 8;
    const float* in = (PH == 0) ? g_h0 : g_h1;
    const float* wt = (PH == 0) ? g_wt1 : g_wt2;
    float* out = (PH == 0) ? g_h1 : outp;

    const int b = blockIdx.z;
    const int ob = blockIdx.y * 64;
    const int rt = blockIdx.x >> 1, ct = blockIdx.x & 1;
    const int r0 = rt * 8, c0col = ct * 32;

    const int tid = threadIdx.x;
    const int warp = tid >> 5, lane = tid & 31;
    const int g = lane >> 2, t = lane & 3;
    const int wm = warp;

    extern __shared__ unsigned smemd[];
    const unsigned smem0 = (unsigned)__cvta_generic_to_shared(smemd);

    // hoisted staging state (constant across chunks)
    const int tx = lane;                   // col within staged row
    const int tg = warp;                   // row-group selector
    const int gx1 = c0col + tx - 1;
    const int gx2 = c0col + 32 + tx - 1;
    const bool ok1 = (gx1 >= 0) && (gx1 < kW);
    const bool ok2 = (tx < 4) && (gx2 < kW);
    const float* inb = in + (size_t)b * IC * kHWp;   // + chunk*8*kHWp per stage
    const float* wtb = wt + ob;

    auto stage = [&](int ci, int bufi) {
        const unsigned sxb = smem0 + (unsigned)(bufi * 8064 * 4);
        const float* inc = inb + (size_t)ci * 8 * kHWp;
#pragma unroll
        for (int c = 0; c < 8; c++) {
#pragma unroll
            for (int y = 0; y < 10; y++) {
                if (((c * 10 + y) & 3) != tg) continue;
                const int gy = r0 + y - 1;
                const bool oky = (gy >= 0) && (gy < kH);
                const float* rp = inc + (size_t)c * kHWp + gy * kW;
                const bool p1 = oky && ok1;
                cp4(sxb + (unsigned)(((c * 10 + y) * 36 + tx) << 2), p1 ? (rp + gx1) : inc, p1 ? 4 : 0);
                if (tx < 4) {
                    const bool p2 = oky && ok2;
                    cp4(sxb + (unsigned)(((c * 10 + y) * 36 + 32 + tx) << 2), p2 ? (rp + gx2) : inc, p2 ? 4 : 0);
                }
            }
        }
        const float* wp = wtb + (size_t)ci * 72 * OC;
        const unsigned swb = sxb + 2880 * 4;
#pragma unroll
        for (int k = 0; k < 9; k++) {
            const int i = tid + k * 128;
            const int row = i >> 4, q = (i & 15) << 2;
            cp16(swb + (unsigned)((row * 72 + q) << 2), wp + (size_t)row * OC + q);
        }
    };

    float acc[4][8][4];
#pragma unroll
    for (int i = 0; i < 4; i++)
#pragma unroll
        for (int j = 0; j < 8; j++)
#pragma unroll
            for (int k = 0; k < 4; k++) acc[i][j][k] = 0.f;

    stage(0, 0); cp_commit();
    stage(1, 1); cp_commit();

    for (int ci = 0; ci < NCH; ci++) {
        if (ci + 2 < NCH) stage(ci + 2, (ci + 2) % 3);
        cp_commit();
        cp_wait2();
        __syncthreads();
        const unsigned* buf = smemd + (ci % 3) * 8064;
#pragma unroll
        for (int dy = 0; dy < 3; dy++) {
#pragma unroll
            for (int dx = 0; dx < 3; dx++) {
                unsigned afr[4][4];
#pragma unroll
                for (int mf = 0; mf < 4; mf++) {
                    const int ys = wm * 2 + (mf >> 1) + dy;
                    const int xb = (mf & 1) * 16 + g + dx;
                    afr[mf][0] = buf[t * 360 + ys * 36 + xb];
                    afr[mf][1] = buf[t * 360 + ys * 36 + xb + 8];
                    afr[mf][2] = buf[(t + 4) * 360 + ys * 36 + xb];
                    afr[mf][3] = buf[(t + 4) * 360 + ys * 36 + xb + 8];
                }
                const int tap = dy * 3 + dx;
                unsigned bfr[8][2];
#pragma unroll
                for (int nf = 0; nf < 8; nf++) {
                    bfr[nf][0] = buf[2880 + (t * 9 + tap) * 72 + nf * 8 + g];
                    bfr[nf][1] = buf[2880 + ((t + 4) * 9 + tap) * 72 + nf * 8 + g];
                }
#pragma unroll
                for (int mf = 0; mf < 4; mf++)
#pragma unroll
                    for (int nf = 0; nf < 8; nf++)
                        mma_tf32(acc[mf][nf], afr[mf], bfr[nf]);
            }
        }
        __syncthreads();
    }

    // epilogue
#pragma unroll
    for (int mf = 0; mf < 4; mf++) {
        const int gy = r0 + wm * 2 + (mf >> 1);
        const int gxA = c0col + (mf & 1) * 16 + g;
        const int gxB = gxA + 8;
        const bool okA = gxA < kW, okB = gxB < kW;
#pragma unroll
        for (int nf = 0; nf < 8; nf++) {
            const int o = ob + nf * 8 + 2 * t;
            const float bv0 = bias[o], bv1 = bias[o + 1];
            float v00 = acc[mf][nf][0] + bv0;
            float v01 = acc[mf][nf][1] + bv1;
            float v10 = acc[mf][nf][2] + bv0;
            float v11 = acc[mf][nf][3] + bv1;
            const size_t base0 = ((size_t)(b * OC + o) * kH + gy) * kW;
            const size_t base1 = ((size_t)(b * OC + o + 1) * kH + gy) * kW;
            if (PH == 0) {
                if (okA) {
                    float a0 = 0.5f * v00 * (1.f + erff(v00 * 0.70710678118654752f));
                    float a1 = 0.5f * v01 * (1.f + erff(v01 * 0.70710678118654752f));
                    out[base0 + gxA] = __uint_as_float(f2tf32(a0));
                    out[base1 + gxA] = __uint_as_float(f2tf32(a1));
                }
                if (okB) {
                    float a2 = 0.5f * v10 * (1.f + erff(v10 * 0.70710678118654752f));
                    float a3 = 0.5f * v11 * (1.f + erff(v11 * 0.70710678118654752f));
                    out[base0 + gxB] = __uint_as_float(f2tf32(a2));
                    out[base1 + gxB] = __uint_as_float(f2tf32(a3));
                }
            } else {
                if (okA) {
                    out[base0 + gxA] = v00 + g_x1[base0 + gxA];
                    out[base1 + gxA] = v01 + g_x1[base1 + gxA];
                }
                if (okB) {
                    out[base0 + gxB] = v10 + g_x1[base0 + gxB];
                    out[base1 + gxB] = v11 + g_x1[base1 + gxB];
                }
            }
        }
    }
}

// ---------------- launch -----------------------------------------------------
extern "C" void kernel_launch(void* const* d_in, const int* in_sizes, int n_in,
                              void* d_out, int out_size) {
    (void)in_sizes; (void)n_in; (void)out_size;
    const float* x       = (const float*)d_in[0];
    const float* ln1_g   = (const float*)d_in[1];
    const float* ln1_b   = (const float*)d_in[2];
    const float* qkv_w   = (const float*)d_in[3];
    const float* qkv_b   = (const float*)d_in[4];
    const float* proj_w  = (const float*)d_in[5];
    const float* proj_b  = (const float*)d_in[6];
    const float* ln2_g   = (const float*)d_in[7];
    const float* ln2_b   = (const float*)d_in[8];
    const float* conv1_w = (const float*)d_in[9];
    const float* conv1_b = (const float*)d_in[10];
    const float* conv2_w = (const float*)d_in[11];
    const float* conv2_b = (const float*)d_in[12];
    float* out = (float*)d_out;

    constexpr int kConvSmem = 3 * 8064 * 4;   // 96768 B
    constexpr int kGemmSmem = 3 * 6400 * 4;   // 76800 B
    static bool attr_done = false;
    if (!attr_done) {
        cudaFuncSetAttribute(conv3x3_mma_kernel<0>, cudaFuncAttributeMaxDynamicSharedMemorySize, kConvSmem);
        cudaFuncSetAttribute(conv3x3_mma_kernel<1>, cudaFuncAttributeMaxDynamicSharedMemorySize, kConvSmem);
        cudaFuncSetAttribute(gemm_mma_kernel<0>, cudaFuncAttributeMaxDynamicSharedMemorySize, kGemmSmem);
        cudaFuncSetAttribute(gemm_mma_kernel<1>, cudaFuncAttributeMaxDynamicSharedMemorySize, kGemmSmem);
        attr_done = true;
    }

    wtrans_kernel<0><<<(kHid * kC * 9 + 255) / 256, 256>>>(conv1_w);
    wtrans_kernel<1><<<(kC * kHid * 9 + 255) / 256, 256>>>(conv2_w);
    wround_kernel<0><<<(3 * kC * kC + 255) / 256, 256>>>(qkv_w);
    wround_kernel<1><<<(kC * kC + 255) / 256, 256>>>(proj_w);

    ln_kernel<0><<<kNT / 256, 256>>>(x, ln1_g, ln1_b);
    gemm_mma_kernel<0><<<dim3(kNT / 256, 9), 128, kGemmSmem>>>(qkv_b, nullptr);
    attn_kernel<<<kNWin * kHeads, 64>>>();
    gemm_mma_kernel<1><<<dim3(kNT / 256, 3), 128, kGemmSmem>>>(proj_b, x);
    ln_kernel<1><<<kNT / 256, 256>>>(nullptr, ln2_g, ln2_b);
    conv3x3_mma_kernel<0><<<dim3(14, kHid / 64, kB), 128, kConvSmem>>>(conv1_b, nullptr);
    conv3x3_mma_kernel<1><<<dim3(14, kC / 64, kB), 128, kConvSmem>>>(conv2_b, out);
}

// round 6
// speedup vs baseline: 1.4258x; 1.4258x over previous
#include <cuda_runtime.h>
#include <math.h>

namespace {
constexpr int kB = 32, kC = 192, kH = 56, kW = 56;
constexpr int kHeads = 6, kD = 32, kWS = 7, kShift = 3, kHid = 768;
constexpr int kNWin = kB * 8 * 8;   // 2048 windows
constexpr int kTok = kWS * kWS;     // 49
constexpr int kNT = kNWin * kTok;   // 100352 tokens
constexpr int kHWp = kH * kW;       // 3136
}

// ---------------- scratch (static __device__, allocation-free) ----------------
__device__ float g_wt1[kC * 9 * kHid];          // conv1 weights transposed, tf32-rounded
__device__ float g_wt2[kHid * 9 * kC];
__device__ float g_xw[(size_t)kNT * kC];        // LN1 out, window layout [win][tok][c]
__device__ float g_q [(size_t)kNT * kC];
__device__ float g_kk[(size_t)kNT * kC];
__device__ float g_vv[(size_t)kNT * kC];
__device__ float g_ao[(size_t)kNT * kC];        // attention out [win][tok][c]
__device__ float g_x1[(size_t)kNT * kC];        // x + attn branch (NCHW)
__device__ float g_h0[(size_t)kNT * kC];        // LN2 out (NCHW), tf32-rounded
__device__ float g_h1[(size_t)kNT * kHid];      // conv1+gelu out (NCHW), tf32-rounded

// ---------------- helpers ----------------------------------------------------
__device__ __forceinline__ unsigned f2tf32(float x) {
    unsigned r; asm("cvt.rna.tf32.f32 %0, %1;" : "=r"(r) : "f"(x)); return r;
}
__device__ __forceinline__ void mma_tf32(float* d, const unsigned* a, const unsigned* b) {
    asm volatile(
        "mma.sync.aligned.m16n8k8.row.col.f32.tf32.tf32.f32 "
        "{%0,%1,%2,%3}, {%4,%5,%6,%7}, {%8,%9}, {%0,%1,%2,%3};\n"
        : "+f"(d[0]), "+f"(d[1]), "+f"(d[2]), "+f"(d[3])
        : "r"(a[0]), "r"(a[1]), "r"(a[2]), "r"(a[3]), "r"(b[0]), "r"(b[1]));
}
__device__ __forceinline__ void cp4(unsigned dst, const void* src, int sz) {
    asm volatile("cp.async.ca.shared.global [%0], [%1], 4, %2;" :: "r"(dst), "l"(src), "r"(sz));
}
__device__ __forceinline__ void cp16(unsigned dst, const void* src) {
    asm volatile("cp.async.cg.shared.global [%0], [%1], 16;" :: "r"(dst), "l"(src));
}

// ---------------- weight transpose:  w[o][c][t] -> wt[(c*9+t)*OC + o] --------
template<int PH>
__global__ void wtrans_kernel(const float* __restrict__ w) {
    constexpr int OC = (PH == 0) ? kHid : kC;
    constexpr int IC = (PH == 0) ? kC : kHid;
    float* wt = (PH == 0) ? g_wt1 : g_wt2;
    int i = blockIdx.x * 256 + threadIdx.x;
    if (i < OC * IC * 9) {
        int o = i / (IC * 9);
        int ct = i - o * (IC * 9);
        wt[(size_t)ct * OC + o] = __uint_as_float(f2tf32(w[i]));
    }
}

// ---------------- LayerNorm over C; MODE 0: x -> g_xw (roll + window) --------
// ----------------                    MODE 1: g_x1 -> g_h0 (tf32-rounded) -----
template<int MODE>
__global__ void ln_kernel(const float* __restrict__ xin,
                          const float* __restrict__ gam,
                          const float* __restrict__ bet) {
    int p = blockIdx.x * 256 + threadIdx.x;
    if (p >= kNT) return;
    const float* src = (MODE == 0) ? xin : g_x1;
    int b = p / kHWp;
    int rem = p - b * kHWp;
    int hp = rem / kW, wp = rem - (rem / kW) * kW;
    int h = hp, w = wp;
    if (MODE == 0) {
        h = hp + kShift; if (h >= kH) h -= kH;
        w = wp + kShift; if (w >= kW) w -= kW;
    }
    const float* xp = src + ((size_t)b * kC) * kHWp + h * kW + w;
    float s = 0.f, s2 = 0.f;
#pragma unroll 4
    for (int c = 0; c < kC; c++) { float v = xp[(size_t)c * kHWp]; s += v; s2 += v * v; }
    float m = s * (1.f / kC);
    float var = s2 * (1.f / kC) - m * m;
    float rs = rsqrtf(var + 1e-5f);
    if (MODE == 0) {
        int win = b * 64 + (hp / 7) * 8 + (wp / 7);
        int tok = (hp % 7) * 7 + (wp % 7);
        float* op = g_xw + ((size_t)win * kTok + tok) * kC;
#pragma unroll 4
        for (int c = 0; c < kC; c++)
            op[c] = (xp[(size_t)c * kHWp] - m) * rs * gam[c] + bet[c];
    } else {
        float* op = g_h0 + ((size_t)b * kC) * kHWp + h * kW + w;
#pragma unroll 4
        for (int c = 0; c < kC; c++) {
            float v = (xp[(size_t)c * kHWp] - m) * rs * gam[c] + bet[c];
            op[(size_t)c * kHWp] = __uint_as_float(f2tf32(v));
        }
    }
}

// ---------------- GEMM via tf32 MMA: 128 thr, warp = 64 tok x 64 out ---------
// Block tile 256 tok x 64 out. EPI 0: A=g_xw -> q/k/v. EPI 1: A=g_ao -> resid.
template<int EPI>
__global__ __launch_bounds__(128, 2) void gemm_mma_kernel(const float* __restrict__ Wm,
                                                          const float* __restrict__ bias,
                                                          const float* __restrict__ xin) {
    __shared__ unsigned sA[16][264];
    __shared__ unsigned sW[16][72];
    const float* A = (EPI == 0) ? g_xw : g_ao;
    const int tid = threadIdx.x;
    const int warp = tid >> 5, lane = tid & 31;
    const int g = lane >> 2, t = lane & 3;
    const int wm = warp;                 // 0..3, 64 tokens each
    const int tokbase = blockIdx.x * 256;
    const int ob = blockIdx.y * 64;

    float acc[4][8][4];
#pragma unroll
    for (int i = 0; i < 4; i++)
#pragma unroll
        for (int j = 0; j < 8; j++)
#pragma unroll
            for (int k = 0; k < 4; k++) acc[i][j][k] = 0.f;

    for (int k0 = 0; k0 < kC; k0 += 16) {
        __syncthreads();
#pragma unroll
        for (int i = tid; i < 1024; i += 128) {
            int tl = i >> 2, kq = (i & 3) << 2;
            float4 v = *(const float4*)(A + (size_t)(tokbase + tl) * kC + k0 + kq);
            sA[kq + 0][tl] = f2tf32(v.x);
            sA[kq + 1][tl] = f2tf32(v.y);
            sA[kq + 2][tl] = f2tf32(v.z);
            sA[kq + 3][tl] = f2tf32(v.w);
        }
#pragma unroll
        for (int i = tid; i < 256; i += 128) {
            int n = i >> 2, kq = (i & 3) << 2;
            float4 v = *(const float4*)(Wm + (size_t)(ob + n) * kC + k0 + kq);
            sW[kq + 0][n] = f2tf32(v.x);
            sW[kq + 1][n] = f2tf32(v.y);
            sW[kq + 2][n] = f2tf32(v.z);
            sW[kq + 3][n] = f2tf32(v.w);
        }
        __syncthreads();
#pragma unroll
        for (int s = 0; s < 2; s++) {
            unsigned afr[4][4];
#pragma unroll
            for (int mf = 0; mf < 4; mf++) {
                const int mbase = wm * 64 + mf * 16;
                afr[mf][0] = sA[s * 8 + t    ][mbase + g];
                afr[mf][1] = sA[s * 8 + t    ][mbase + g + 8];
                afr[mf][2] = sA[s * 8 + t + 4][mbase + g];
                afr[mf][3] = sA[s * 8 + t + 4][mbase + g + 8];
            }
            unsigned bfr[8][2];
#pragma unroll
            for (int nf = 0; nf < 8; nf++) {
                bfr[nf][0] = sW[s * 8 + t    ][nf * 8 + g];
                bfr[nf][1] = sW[s * 8 + t + 4][nf * 8 + g];
            }
#pragma unroll
            for (int mf = 0; mf < 4; mf++)
#pragma unroll
                for (int nf = 0; nf < 8; nf++)
                    mma_tf32(acc[mf][nf], afr[mf], bfr[nf]);
        }
    }

#pragma unroll
    for (int mf = 0; mf < 4; mf++) {
        const int tk0 = tokbase + wm * 64 + mf * 16 + g;
#pragma unroll
        for (int nf = 0; nf < 8; nf++) {
            const int o0 = ob + nf * 8 + 2 * t;
            const float bv0 = bias[o0], bv1 = bias[o0 + 1];
            float vals[4] = {acc[mf][nf][0] + bv0, acc[mf][nf][1] + bv1,
                             acc[mf][nf][2] + bv0, acc[mf][nf][3] + bv1};
#pragma unroll
            for (int q = 0; q < 4; q++) {
                const int n_tok = tk0 + (q >> 1) * 8;
                const int mo = o0 + (q & 1);
                const int win = n_tok / 49, tok = n_tok - win * 49;
                if (EPI == 0) {
                    int sec = mo / kC;
                    int c = mo - sec * kC;
                    float* dst = (sec == 0) ? g_q : (sec == 1) ? g_kk : g_vv;
                    dst[((size_t)(win * kHeads + (c >> 5)) * kTok + tok) * kD + (c & 31)] = vals[q];
                } else {
                    int bb  = win >> 6;
                    int whh = (win >> 3) & 7;
                    int www = win & 7;
                    int ti = tok / 7, tj = tok - ti * 7;
                    int hi = whh * 7 + ti + kShift; if (hi >= kH) hi -= kH;
                    int wi = www * 7 + tj + kShift; if (wi >= kW) wi -= kW;
                    size_t idx = ((size_t)(bb * kC + mo) * kH + hi) * kW + wi;
                    g_x1[idx] = xin[idx] + vals[q];
                }
            }
        }
    }
}

// ---------------- attention: one block per (window, head), scores in regs ----
__global__ __launch_bounds__(64) void attn_kernel() {
    const int wh = blockIdx.x;
    __shared__ float sq[kTok * 33], sk[kTok * kD], sv[kTok * kD];
    const size_t base = (size_t)wh * kTok * kD;
    for (int i = threadIdx.x; i < kTok * kD; i += 64) {
        int r = i >> 5, d = i & 31;
        sq[r * 33 + d] = g_q[base + i];
        sk[i] = g_kk[base + i];
        sv[i] = g_vv[base + i];
    }
    __syncthreads();
    const int r = threadIdx.x;
    if (r < kTok) {
        float qr[kD];
#pragma unroll
        for (int d = 0; d < kD; d++) qr[d] = sq[r * 33 + d];
        float p[kTok];
        float mx = -1e30f;
#pragma unroll
        for (int m = 0; m < kTok; m++) {
            float dot = 0.f;
#pragma unroll
            for (int d = 0; d < kD; d++) dot += qr[d] * sk[m * kD + d];
            dot *= 0.17677669529663689f;
            p[m] = dot;
            mx = fmaxf(mx, dot);
        }
        float sum = 0.f;
#pragma unroll
        for (int m = 0; m < kTok; m++) { p[m] = __expf(p[m] - mx); sum += p[m]; }
        const float inv = 1.f / sum;
        const int win = wh / kHeads, head = wh - win * kHeads;
        float* op = g_ao + ((size_t)win * kTok + r) * kC + head * kD;
#pragma unroll 4
        for (int d = 0; d < kD; d++) {
            float a = 0.f;
#pragma unroll
            for (int m = 0; m < kTok; m++) a += p[m] * sv[m * kD + d];
            op[d] = a * inv;
        }
    }
}

// ---------------- 3x3 conv via tf32 MMA, 3-stage ring, 1 sync/chunk ----------
// 128 thr / 4 warps, block tile 8 rows x 32 cols (256 px) x 64 oc.
// Buffer = sx 8*10*36 (2880 w) + sw 72*72 (5184 w) = 8064 words; 3 buffers.
// Skeleton per chunk: wait(buf ci) -> ONE sync -> stage(ci+2) -> compute(ci).
// stage(ci+2) writes buf (ci-1)%3 whose readers all passed this iteration's
// sync (they finished compute(ci-1) before arriving) => race-free.
template<int PH>
__global__ __launch_bounds__(128, 2) void conv3x3_mma_kernel(const float* __restrict__ bias,
                                                             float* __restrict__ outp) {
    constexpr int IC = (PH == 0) ? kC : kHid;
    constexpr int OC = (PH == 0) ? kHid : kC;
    constexpr int NCH = IC / 8;
    const float* in = (PH == 0) ? g_h0 : g_h1;
    const float* wt = (PH == 0) ? g_wt1 : g_wt2;
    float* out = (PH == 0) ? g_h1 : outp;

    const int b = blockIdx.z;
    const int ob = blockIdx.y * 64;
    const int rt = blockIdx.x >> 1, ct = blockIdx.x & 1;
    const int r0 = rt * 8, c0col = ct * 32;

    const int tid = threadIdx.x;
    const int warp = tid >> 5, lane = tid & 31;
    const int g = lane >> 2, t = lane & 3;
    const int wm = warp;

    extern __shared__ unsigned smemd[];
    const unsigned smem0 = (unsigned)__cvta_generic_to_shared(smemd);

    auto stage = [&](int ci, int bufi) {
        const unsigned sxb = smem0 + (unsigned)(bufi * 8064 * 4);
        const float* inc = in + ((size_t)(b * IC + ci * 8) * kH) * kW;
        for (int i = tid; i < 8 * 340; i += 128) {
            int c = i / 340, rem = i - c * 340;
            int y = rem / 34, x = rem - y * 34;
            int gy = r0 + y - 1, gx = c0col + x - 1;
            bool ok = (gy >= 0 && gy < kH && gx >= 0 && gx < kW);
            const float* src = inc + (size_t)c * kHWp + (ok ? (gy * kW + gx) : 0);
            cp4(sxb + (unsigned)(((c * 10 + y) * 36 + x) << 2), src, ok ? 4 : 0);
        }
        const float* wp = wt + (size_t)(ci * 8) * 9 * OC + ob;
        const unsigned swb = sxb + 2880 * 4;
        for (int i = tid; i < 72 * 16; i += 128) {
            int row = i >> 4, cq = (i & 15) << 2;
            cp16(swb + (unsigned)((row * 72 + cq) << 2), wp + (size_t)row * OC + cq);
        }
        asm volatile("cp.async.commit_group;");
    };

    float acc[4][8][4];
#pragma unroll
    for (int i = 0; i < 4; i++)
#pragma unroll
        for (int j = 0; j < 8; j++)
#pragma unroll
            for (int k = 0; k < 4; k++) acc[i][j][k] = 0.f;

    stage(0, 0);
    stage(1, 1);

    for (int ci = 0; ci < NCH; ci++) {
        // groups outstanding here: stage(ci), stage(ci+1) [if issued]; need stage(ci).
        if (ci + 1 < NCH) asm volatile("cp.async.wait_group 1;");
        else              asm volatile("cp.async.wait_group 0;");
        __syncthreads();
        if (ci + 2 < NCH) stage(ci + 2, (ci + 2) % 3);
        const unsigned* buf = smemd + (ci % 3) * 8064;
#pragma unroll
        for (int dy = 0; dy < 3; dy++) {
#pragma unroll
            for (int dx = 0; dx < 3; dx++) {
                unsigned afr[4][4];
#pragma unroll
                for (int mf = 0; mf < 4; mf++) {
                    const int ys = wm * 2 + (mf >> 1) + dy;
                    const int xb = (mf & 1) * 16 + g + dx;
                    afr[mf][0] = buf[t * 360 + ys * 36 + xb];
                    afr[mf][1] = buf[t * 360 + ys * 36 + xb + 8];
                    afr[mf][2] = buf[(t + 4) * 360 + ys * 36 + xb];
                    afr[mf][3] = buf[(t + 4) * 360 + ys * 36 + xb + 8];
                }
                const int tap = dy * 3 + dx;
                unsigned bfr[8][2];
#pragma unroll
                for (int nf = 0; nf < 8; nf++) {
                    bfr[nf][0] = buf[2880 + (t * 9 + tap) * 72 + nf * 8 + g];
                    bfr[nf][1] = buf[2880 + ((t + 4) * 9 + tap) * 72 + nf * 8 + g];
                }
#pragma unroll
                for (int mf = 0; mf < 4; mf++)
#pragma unroll
                    for (int nf = 0; nf < 8; nf++)
                        mma_tf32(acc[mf][nf], afr[mf], bfr[nf]);
            }
        }
    }

    // epilogue
#pragma unroll
    for (int mf = 0; mf < 4; mf++) {
        const int gy = r0 + wm * 2 + (mf >> 1);
        const int gxA = c0col + (mf & 1) * 16 + g;
        const int gxB = gxA + 8;
        const bool okA = gxA < kW, okB = gxB < kW;
#pragma unroll
        for (int nf = 0; nf < 8; nf++) {
            const int o = ob + nf * 8 + 2 * t;
            const float bv0 = bias[o], bv1 = bias[o + 1];
            float v00 = acc[mf][nf][0] + bv0;
            float v01 = acc[mf][nf][1] + bv1;
            float v10 = acc[mf][nf][2] + bv0;
            float v11 = acc[mf][nf][3] + bv1;
            const size_t base0 = ((size_t)(b * OC + o) * kH + gy) * kW;
            const size_t base1 = ((size_t)(b * OC + o + 1) * kH + gy) * kW;
            if (PH == 0) {
                if (okA) {
                    float a0 = 0.5f * v00 * (1.f + erff(v00 * 0.70710678118654752f));
                    float a1 = 0.5f * v01 * (1.f + erff(v01 * 0.70710678118654752f));
                    out[base0 + gxA] = __uint_as_float(f2tf32(a0));
                    out[base1 + gxA] = __uint_as_float(f2tf32(a1));
                }
                if (okB) {
                    float a2 = 0.5f * v10 * (1.f + erff(v10 * 0.70710678118654752f));
                    float a3 = 0.5f * v11 * (1.f + erff(v11 * 0.70710678118654752f));
                    out[base0 + gxB] = __uint_as_float(f2tf32(a2));
                    out[base1 + gxB] = __uint_as_float(f2tf32(a3));
                }
            } else {
                if (okA) {
                    out[base0 + gxA] = v00 + g_x1[base0 + gxA];
                    out[base1 + gxA] = v01 + g_x1[base1 + gxA];
                }
                if (okB) {
                    out[base0 + gxB] = v10 + g_x1[base0 + gxB];
                    out[base1 + gxB] = v11 + g_x1[base1 + gxB];
                }
            }
        }
    }
}

// ---------------- launch -----------------------------------------------------
extern "C" void kernel_launch(void* const* d_in, const int* in_sizes, int n_in,
                              void* d_out, int out_size) {
    (void)in_sizes; (void)n_in; (void)out_size;
    const float* x       = (const float*)d_in[0];
    const float* ln1_g   = (const float*)d_in[1];
    const float* ln1_b   = (const float*)d_in[2];
    const float* qkv_w   = (const float*)d_in[3];
    const float* qkv_b   = (const float*)d_in[4];
    const float* proj_w  = (const float*)d_in[5];
    const float* proj_b  = (const float*)d_in[6];
    const float* ln2_g   = (const float*)d_in[7];
    const float* ln2_b   = (const float*)d_in[8];
    const float* conv1_w = (const float*)d_in[9];
    const float* conv1_b = (const float*)d_in[10];
    const float* conv2_w = (const float*)d_in[11];
    const float* conv2_b = (const float*)d_in[12];
    float* out = (float*)d_out;

    constexpr int kConvSmem = 3 * 8064 * 4;   // 96768 B
    static bool attr_done = false;
    if (!attr_done) {
        cudaFuncSetAttribute(conv3x3_mma_kernel<0>, cudaFuncAttributeMaxDynamicSharedMemorySize, kConvSmem);
        cudaFuncSetAttribute(conv3x3_mma_kernel<1>, cudaFuncAttributeMaxDynamicSharedMemorySize, kConvSmem);
        attr_done = true;
    }

    wtrans_kernel<0><<<(kHid * kC * 9 + 255) / 256, 256>>>(conv1_w);
    wtrans_kernel<1><<<(kC * kHid * 9 + 255) / 256, 256>>>(conv2_w);

    ln_kernel<0><<<kNT / 256, 256>>>(x, ln1_g, ln1_b);
    gemm_mma_kernel<0><<<dim3(kNT / 256, 9), 128>>>(qkv_w, qkv_b, nullptr);
    attn_kernel<<<kNWin * kHeads, 64>>>();
    gemm_mma_kernel<1><<<dim3(kNT / 256, 3), 128>>>(proj_w, proj_b, x);
    ln_kernel<1><<<kNT / 256, 256>>>(nullptr, ln2_g, ln2_b);
    conv3x3_mma_kernel<0><<<dim3(14, kHid / 64, kB), 128, kConvSmem>>>(conv1_b, nullptr);
    conv3x3_mma_kernel<1><<<dim3(14, kC / 64, kB), 128, kConvSmem>>>(conv2_b, out);
}

// round 7
// speedup vs baseline: 1.4358x; 1.0070x over previous
#include <cuda_runtime.h>
#include <math.h>

namespace {
constexpr int kB = 32, kC = 192, kH = 56, kW = 56;
constexpr int kHeads = 6, kD = 32, kWS = 7, kShift = 3, kHid = 768;
constexpr int kNWin = kB * 8 * 8;   // 2048 windows
constexpr int kTok = kWS * kWS;     // 49
constexpr int kNT = kNWin * kTok;   // 100352 tokens
constexpr int kHWp = kH * kW;       // 3136
}

// ---------------- scratch (static __device__, allocation-free) ----------------
__device__ float g_wt1[kC * 9 * kHid];          // conv1 weights transposed, tf32-rounded
__device__ float g_wt2[kHid * 9 * kC];
__device__ float g_xw[(size_t)kNT * kC];        // LN1 out, window layout [win][tok][c]
__device__ float g_q [(size_t)kNT * kC];
__device__ float g_kk[(size_t)kNT * kC];
__device__ float g_vv[(size_t)kNT * kC];
__device__ float g_ao[(size_t)kNT * kC];        // attention out [win][tok][c]
__device__ float g_x1[(size_t)kNT * kC];        // x + attn branch (NCHW)
__device__ float g_h0[(size_t)kNT * kC];        // LN2 out (NCHW), tf32-rounded
__device__ float g_h1[(size_t)kNT * kHid];      // conv1+gelu out (NCHW), tf32-rounded

// ---------------- helpers ----------------------------------------------------
__device__ __forceinline__ unsigned f2tf32(float x) {
    unsigned r; asm("cvt.rna.tf32.f32 %0, %1;" : "=r"(r) : "f"(x)); return r;
}
__device__ __forceinline__ void mma_tf32(float* d, const unsigned* a, const unsigned* b) {
    asm volatile(
        "mma.sync.aligned.m16n8k8.row.col.f32.tf32.tf32.f32 "
        "{%0,%1,%2,%3}, {%4,%5,%6,%7}, {%8,%9}, {%0,%1,%2,%3};\n"
        : "+f"(d[0]), "+f"(d[1]), "+f"(d[2]), "+f"(d[3])
        : "r"(a[0]), "r"(a[1]), "r"(a[2]), "r"(a[3]), "r"(b[0]), "r"(b[1]));
}
__device__ __forceinline__ void cp4(unsigned dst, const void* src, int sz) {
    asm volatile("cp.async.ca.shared.global [%0], [%1], 4, %2;" :: "r"(dst), "l"(src), "r"(sz));
}
__device__ __forceinline__ void cp16(unsigned dst, const void* src) {
    asm volatile("cp.async.cg.shared.global [%0], [%1], 16;" :: "r"(dst), "l"(src));
}

// ---------------- weight transpose:  w[o][c][t] -> wt[(c*9+t)*OC + o] --------
template<int PH>
__global__ void wtrans_kernel(const float* __restrict__ w) {
    constexpr int OC = (PH == 0) ? kHid : kC;
    constexpr int IC = (PH == 0) ? kC : kHid;
    float* wt = (PH == 0) ? g_wt1 : g_wt2;
    int i = blockIdx.x * 256 + threadIdx.x;
    if (i < OC * IC * 9) {
        int o = i / (IC * 9);
        int ct = i - o * (IC * 9);
        wt[(size_t)ct * OC + o] = __uint_as_float(f2tf32(w[i]));
    }
}

// ---------------- LayerNorm over C; MODE 0: x -> g_xw (roll + window) --------
// ----------------                    MODE 1: g_x1 -> g_h0 (tf32-rounded) -----
template<int MODE>
__global__ void ln_kernel(const float* __restrict__ xin,
                          const float* __restrict__ gam,
                          const float* __restrict__ bet) {
    int p = blockIdx.x * 256 + threadIdx.x;
    if (p >= kNT) return;
    const float* src = (MODE == 0) ? xin : g_x1;
    int b = p / kHWp;
    int rem = p - b * kHWp;
    int hp = rem / kW, wp = rem - (rem / kW) * kW;
    int h = hp, w = wp;
    if (MODE == 0) {
        h = hp + kShift; if (h >= kH) h -= kH;
        w = wp + kShift; if (w >= kW) w -= kW;
    }
    const float* xp = src + ((size_t)b * kC) * kHWp + h * kW + w;
    float s = 0.f, s2 = 0.f;
#pragma unroll 4
    for (int c = 0; c < kC; c++) { float v = xp[(size_t)c * kHWp]; s += v; s2 += v * v; }
    float m = s * (1.f / kC);
    float var = s2 * (1.f / kC) - m * m;
    float rs = rsqrtf(var + 1e-5f);
    if (MODE == 0) {
        int win = b * 64 + (hp / 7) * 8 + (wp / 7);
        int tok = (hp % 7) * 7 + (wp % 7);
        float* op = g_xw + ((size_t)win * kTok + tok) * kC;
#pragma unroll 4
        for (int c = 0; c < kC; c++)
            op[c] = (xp[(size_t)c * kHWp] - m) * rs * gam[c] + bet[c];
    } else {
        float* op = g_h0 + ((size_t)b * kC) * kHWp + h * kW + w;
#pragma unroll 4
        for (int c = 0; c < kC; c++) {
            float v = (xp[(size_t)c * kHWp] - m) * rs * gam[c] + bet[c];
            op[(size_t)c * kHWp] = __uint_as_float(f2tf32(v));
        }
    }
}

// ---------------- GEMM via tf32 MMA: 128 thr, warp = 64 tok x 64 out ---------
// Block tile 256 tok x 64 out. EPI 0: A=g_xw -> q/k/v. EPI 1: A=g_ao -> resid.
template<int EPI>
__global__ __launch_bounds__(128, 2) void gemm_mma_kernel(const float* __restrict__ Wm,
                                                          const float* __restrict__ bias,
                                                          const float* __restrict__ xin) {
    __shared__ unsigned sA[16][264];
    __shared__ unsigned sW[16][72];
    const float* A = (EPI == 0) ? g_xw : g_ao;
    const int tid = threadIdx.x;
    const int warp = tid >> 5, lane = tid & 31;
    const int g = lane >> 2, t = lane & 3;
    const int wm = warp;                 // 0..3, 64 tokens each
    const int tokbase = blockIdx.x * 256;
    const int ob = blockIdx.y * 64;

    float acc[4][8][4];
#pragma unroll
    for (int i = 0; i < 4; i++)
#pragma unroll
        for (int j = 0; j < 8; j++)
#pragma unroll
            for (int k = 0; k < 4; k++) acc[i][j][k] = 0.f;

    for (int k0 = 0; k0 < kC; k0 += 16) {
        __syncthreads();
#pragma unroll
        for (int i = tid; i < 1024; i += 128) {
            int tl = i >> 2, kq = (i & 3) << 2;
            float4 v = *(const float4*)(A + (size_t)(tokbase + tl) * kC + k0 + kq);
            sA[kq + 0][tl] = f2tf32(v.x);
            sA[kq + 1][tl] = f2tf32(v.y);
            sA[kq + 2][tl] = f2tf32(v.z);
            sA[kq + 3][tl] = f2tf32(v.w);
        }
#pragma unroll
        for (int i = tid; i < 256; i += 128) {
            int n = i >> 2, kq = (i & 3) << 2;
            float4 v = *(const float4*)(Wm + (size_t)(ob + n) * kC + k0 + kq);
            sW[kq + 0][n] = f2tf32(v.x);
            sW[kq + 1][n] = f2tf32(v.y);
            sW[kq + 2][n] = f2tf32(v.z);
            sW[kq + 3][n] = f2tf32(v.w);
        }
        __syncthreads();
#pragma unroll
        for (int s = 0; s < 2; s++) {
            unsigned afr[4][4];
#pragma unroll
            for (int mf = 0; mf < 4; mf++) {
                const int mbase = wm * 64 + mf * 16;
                afr[mf][0] = sA[s * 8 + t    ][mbase + g];
                afr[mf][1] = sA[s * 8 + t    ][mbase + g + 8];
                afr[mf][2] = sA[s * 8 + t + 4][mbase + g];
                afr[mf][3] = sA[s * 8 + t + 4][mbase + g + 8];
            }
            unsigned bfr[8][2];
#pragma unroll
            for (int nf = 0; nf < 8; nf++) {
                bfr[nf][0] = sW[s * 8 + t    ][nf * 8 + g];
                bfr[nf][1] = sW[s * 8 + t + 4][nf * 8 + g];
            }
#pragma unroll
            for (int mf = 0; mf < 4; mf++)
#pragma unroll
                for (int nf = 0; nf < 8; nf++)
                    mma_tf32(acc[mf][nf], afr[mf], bfr[nf]);
        }
    }

#pragma unroll
    for (int mf = 0; mf < 4; mf++) {
        const int tk0 = tokbase + wm * 64 + mf * 16 + g;
#pragma unroll
        for (int nf = 0; nf < 8; nf++) {
            const int o0 = ob + nf * 8 + 2 * t;
            const float bv0 = bias[o0], bv1 = bias[o0 + 1];
            float vals[4] = {acc[mf][nf][0] + bv0, acc[mf][nf][1] + bv1,
                             acc[mf][nf][2] + bv0, acc[mf][nf][3] + bv1};
#pragma unroll
            for (int q = 0; q < 4; q++) {
                const int n_tok = tk0 + (q >> 1) * 8;
                const int mo = o0 + (q & 1);
                const int win = n_tok / 49, tok = n_tok - win * 49;
                if (EPI == 0) {
                    int sec = mo / kC;
                    int c = mo - sec * kC;
                    float* dst = (sec == 0) ? g_q : (sec == 1) ? g_kk : g_vv;
                    dst[((size_t)(win * kHeads + (c >> 5)) * kTok + tok) * kD + (c & 31)] = vals[q];
                } else {
                    int bb  = win >> 6;
                    int whh = (win >> 3) & 7;
                    int www = win & 7;
                    int ti = tok / 7, tj = tok - ti * 7;
                    int hi = whh * 7 + ti + kShift; if (hi >= kH) hi -= kH;
                    int wi = www * 7 + tj + kShift; if (wi >= kW) wi -= kW;
                    size_t idx = ((size_t)(bb * kC + mo) * kH + hi) * kW + wi;
                    g_x1[idx] = xin[idx] + vals[q];
                }
            }
        }
    }
}

// ---------------- attention: one block per (window, head), scores in regs ----
__global__ __launch_bounds__(64) void attn_kernel() {
    const int wh = blockIdx.x;
    __shared__ float sq[kTok * 33], sk[kTok * kD], sv[kTok * kD];
    const size_t base = (size_t)wh * kTok * kD;
    for (int i = threadIdx.x; i < kTok * kD; i += 64) {
        int r = i >> 5, d = i & 31;
        sq[r * 33 + d] = g_q[base + i];
        sk[i] = g_kk[base + i];
        sv[i] = g_vv[base + i];
    }
    __syncthreads();
    const int r = threadIdx.x;
    if (r < kTok) {
        float qr[kD];
#pragma unroll
        for (int d = 0; d < kD; d++) qr[d] = sq[r * 33 + d];
        float p[kTok];
        float mx = -1e30f;
#pragma unroll
        for (int m = 0; m < kTok; m++) {
            float dot = 0.f;
#pragma unroll
            for (int d = 0; d < kD; d++) dot += qr[d] * sk[m * kD + d];
            dot *= 0.17677669529663689f;
            p[m] = dot;
            mx = fmaxf(mx, dot);
        }
        float sum = 0.f;
#pragma unroll
        for (int m = 0; m < kTok; m++) { p[m] = __expf(p[m] - mx); sum += p[m]; }
        const float inv = 1.f / sum;
        const int win = wh / kHeads, head = wh - win * kHeads;
        float* op = g_ao + ((size_t)win * kTok + r) * kC + head * kD;
#pragma unroll 4
        for (int d = 0; d < kD; d++) {
            float a = 0.f;
#pragma unroll
            for (int m = 0; m < kTok; m++) a += p[m] * sv[m * kD + d];
            op[d] = a * inv;
        }
    }
}

// ---------------- 3x3 conv via tf32 MMA, 3-stage ring, 1 sync/chunk ----------
// 128 thr / 4 warps, block tile 8 rows x 32 cols (256 px) x 64 oc.
// Buffer = sx 8*10*36 (2880 w) + sw 72*72 (5184 w) = 8064 words; 3 buffers.
// Skeleton per chunk: wait(buf ci) -> ONE sync -> stage(ci+2) -> compute(ci).
// stage(ci+2) writes buf (ci-1)%3 whose readers all passed this iteration's
// sync (they finished compute(ci-1) before arriving) => race-free.
template<int PH>
__global__ __launch_bounds__(128, 2) void conv3x3_mma_kernel(const float* __restrict__ bias,
                                                             float* __restrict__ outp) {
    constexpr int IC = (PH == 0) ? kC : kHid;
    constexpr int OC = (PH == 0) ? kHid : kC;
    constexpr int NCH = IC / 8;
    const float* in = (PH == 0) ? g_h0 : g_h1;
    const float* wt = (PH == 0) ? g_wt1 : g_wt2;
    float* out = (PH == 0) ? g_h1 : outp;

    const int b = blockIdx.z;
    const int ob = blockIdx.y * 64;
    const int rt = blockIdx.x >> 1, ct = blockIdx.x & 1;
    const int r0 = rt * 8, c0col = ct * 32;

    const int tid = threadIdx.x;
    const int warp = tid >> 5, lane = tid & 31;
    const int g = lane >> 2, t = lane & 3;
    const int wm = warp;

    extern __shared__ unsigned smemd[];
    const unsigned smem0 = (unsigned)__cvta_generic_to_shared(smemd);

    auto stage = [&](int ci, int bufi) {
        const unsigned sxb = smem0 + (unsigned)(bufi * 8064 * 4);
        const float* inc = in + ((size_t)(b * IC + ci * 8) * kH) * kW;
        for (int i = tid; i < 8 * 340; i += 128) {
            int c = i / 340, rem = i - c * 340;
            int y = rem / 34, x = rem - y * 34;
            int gy = r0 + y - 1, gx = c0col + x - 1;
            bool ok = (gy >= 0 && gy < kH && gx >= 0 && gx < kW);
            const float* src = inc + (size_t)c * kHWp + (ok ? (gy * kW + gx) : 0);
            cp4(sxb + (unsigned)(((c * 10 + y) * 36 + x) << 2), src, ok ? 4 : 0);
        }
        const float* wp = wt + (size_t)(ci * 8) * 9 * OC + ob;
        const unsigned swb = sxb + 2880 * 4;
        for (int i = tid; i < 72 * 16; i += 128) {
            int row = i >> 4, cq = (i & 15) << 2;
            cp16(swb + (unsigned)((row * 72 + cq) << 2), wp + (size_t)row * OC + cq);
        }
        asm volatile("cp.async.commit_group;");
    };

    float acc[4][8][4];
#pragma unroll
    for (int i = 0; i < 4; i++)
#pragma unroll
        for (int j = 0; j < 8; j++)
#pragma unroll
            for (int k = 0; k < 4; k++) acc[i][j][k] = 0.f;

    stage(0, 0);
    stage(1, 1);

    for (int ci = 0; ci < NCH; ci++) {
        // groups outstanding here: stage(ci), stage(ci+1) [if issued]; need stage(ci).
        if (ci + 1 < NCH) asm volatile("cp.async.wait_group 1;");
        else              asm volatile("cp.async.wait_group 0;");
        __syncthreads();
        if (ci + 2 < NCH) stage(ci + 2, (ci + 2) % 3);
        const unsigned* buf = smemd + (ci % 3) * 8064;
#pragma unroll
        for (int dy = 0; dy < 3; dy++) {
#pragma unroll
            for (int dx = 0; dx < 3; dx++) {
                unsigned afr[4][4];
#pragma unroll
                for (int mf = 0; mf < 4; mf++) {
                    const int ys = wm * 2 + (mf >> 1) + dy;
                    const int xb = (mf & 1) * 16 + g + dx;
                    afr[mf][0] = buf[t * 360 + ys * 36 + xb];
                    afr[mf][1] = buf[t * 360 + ys * 36 + xb + 8];
                    afr[mf][2] = buf[(t + 4) * 360 + ys * 36 + xb];
                    afr[mf][3] = buf[(t + 4) * 360 + ys * 36 + xb + 8];
                }
                const int tap = dy * 3 + dx;
                unsigned bfr[8][2];
#pragma unroll
                for (int nf = 0; nf < 8; nf++) {
                    bfr[nf][0] = buf[2880 + (t * 9 + tap) * 72 + nf * 8 + g];
                    bfr[nf][1] = buf[2880 + ((t + 4) * 9 + tap) * 72 + nf * 8 + g];
                }
#pragma unroll
                for (int mf = 0; mf < 4; mf++)
#pragma unroll
                    for (int nf = 0; nf < 8; nf++)
                        mma_tf32(acc[mf][nf], afr[mf], bfr[nf]);
            }
        }
    }

    // epilogue
#pragma unroll
    for (int mf = 0; mf < 4; mf++) {
        const int gy = r0 + wm * 2 + (mf >> 1);
        const int gxA = c0col + (mf & 1) * 16 + g;
        const int gxB = gxA + 8;
        const bool okA = gxA < kW, okB = gxB < kW;
#pragma unroll
        for (int nf = 0; nf < 8; nf++) {
            const int o = ob + nf * 8 + 2 * t;
            const float bv0 = bias[o], bv1 = bias[o + 1];
            float v00 = acc[mf][nf][0] + bv0;
            float v01 = acc[mf][nf][1] + bv1;
            float v10 = acc[mf][nf][2] + bv0;
            float v11 = acc[mf][nf][3] + bv1;
            const size_t base0 = ((size_t)(b * OC + o) * kH + gy) * kW;
            const size_t base1 = ((size_t)(b * OC + o + 1) * kH + gy) * kW;
            if (PH == 0) {
                if (okA) {
                    float a0 = 0.5f * v00 * (1.f + erff(v00 * 0.70710678118654752f));
                    float a1 = 0.5f * v01 * (1.f + erff(v01 * 0.70710678118654752f));
                    out[base0 + gxA] = __uint_as_float(f2tf32(a0));
                    out[base1 + gxA] = __uint_as_float(f2tf32(a1));
                }
                if (okB) {
                    float a2 = 0.5f * v10 * (1.f + erff(v10 * 0.70710678118654752f));
                    float a3 = 0.5f * v11 * (1.f + erff(v11 * 0.70710678118654752f));
                    out[base0 + gxB] = __uint_as_float(f2tf32(a2));
                    out[base1 + gxB] = __uint_as_float(f2tf32(a3));
                }
            } else {
                if (okA) {
                    out[base0 + gxA] = v00 + g_x1[base0 + gxA];
                    out[base1 + gxA] = v01 + g_x1[base1 + gxA];
                }
                if (okB) {
                    out[base0 + gxB] = v10 + g_x1[base0 + gxB];
                    out[base1 + gxB] = v11 + g_x1[base1 + gxB];
                }
            }
        }
    }
}

// ---------------- launch -----------------------------------------------------
extern "C" void kernel_launch(void* const* d_in, const int* in_sizes, int n_in,
                              void* d_out, int out_size) {
    (void)in_sizes; (void)n_in; (void)out_size;
    const float* x       = (const float*)d_in[0];
    const float* ln1_g   = (const float*)d_in[1];
    const float* ln1_b   = (const float*)d_in[2];
    const float* qkv_w   = (const float*)d_in[3];
    const float* qkv_b   = (const float*)d_in[4];
    const float* proj_w  = (const float*)d_in[5];
    const float* proj_b  = (const float*)d_in[6];
    const float* ln2_g   = (const float*)d_in[7];
    const float* ln2_b   = (const float*)d_in[8];
    const float* conv1_w = (const float*)d_in[9];
    const float* conv1_b = (const float*)d_in[10];
    const float* conv2_w = (const float*)d_in[11];
    const float* conv2_b = (const float*)d_in[12];
    float* out = (float*)d_out;

    constexpr int kConvSmem = 3 * 8064 * 4;   // 96768 B
    static bool attr_done = false;
    if (!attr_done) {
        cudaFuncSetAttribute(conv3x3_mma_kernel<0>, cudaFuncAttributeMaxDynamicSharedMemorySize, kConvSmem);
        cudaFuncSetAttribute(conv3x3_mma_kernel<1>, cudaFuncAttributeMaxDynamicSharedMemorySize, kConvSmem);
        attr_done = true;
    }

    wtrans_kernel<0><<<(kHid * kC * 9 + 255) / 256, 256>>>(conv1_w);
    wtrans_kernel<1><<<(kC * kHid * 9 + 255) / 256, 256>>>(conv2_w);

    ln_kernel<0><<<kNT / 256, 256>>>(x, ln1_g, ln1_b);
    gemm_mma_kernel<0><<<dim3(kNT / 256, 9), 128>>>(qkv_w, qkv_b, nullptr);
    attn_kernel<<<kNWin * kHeads, 64>>>();
    gemm_mma_kernel<1><<<dim3(kNT / 256, 3), 128>>>(proj_w, proj_b, x);
    ln_kernel<1><<<kNT / 256, 256>>>(nullptr, ln2_g, ln2_b);
    conv3x3_mma_kernel<0><<<dim3(14, kHid / 64, kB), 128, kConvSmem>>>(conv1_b, nullptr);
    conv3x3_mma_kernel<1><<<dim3(14, kC / 64, kB), 128, kConvSmem>>>(conv2_b, out);
}

// round 9
// speedup vs baseline: 2.1822x; 1.5198x over previous
#include <cuda_runtime.h>
#include <cuda_fp16.h>
#include <math.h>

namespace {
constexpr int kB = 32, kC = 192, kH = 56, kW = 56;
constexpr int kHeads = 6, kD = 32, kWS = 7, kShift = 3, kHid = 768;
constexpr int kNWin = kB * 8 * 8;   // 2048 windows
constexpr int kTok = kWS * kWS;     // 49
constexpr int kNT = kNWin * kTok;   // 100352 tokens
constexpr int kHWp = kH * kW;       // 3136
}

// ---------------- scratch (static __device__, allocation-free) ----------------
__device__ __half g_wf1[1327104];               // conv1 w fp16 tiles [cc][ocb][72][128]
__device__ __half g_wf2[1327104];               // conv2 w fp16 tiles
__device__ float g_xw[(size_t)kNT * kC];        // LN1 out, [win][tok][c]
__device__ float g_q [(size_t)kNT * kC];
__device__ float g_kk[(size_t)kNT * kC];
__device__ float g_vv[(size_t)kNT * kC];
__device__ float g_ao[(size_t)kNT * kC];        // attn out [win][tok][c]
__device__ float g_x1[(size_t)kNT * kC];        // x + attn branch (NCHW)
__device__ __half g_h0[(size_t)kNT * kC];       // LN2 out, NHWC fp16
__device__ __half g_h1[(size_t)kNT * kHid];     // conv1+gelu out, NHWC fp16

// ---------------- helpers ----------------------------------------------------
__device__ __forceinline__ unsigned f2tf32(float x) {
    unsigned r; asm("cvt.rna.tf32.f32 %0, %1;" : "=r"(r) : "f"(x)); return r;
}
__device__ __forceinline__ void mma_tf32(float* d, const unsigned* a, const unsigned* b) {
    asm volatile(
        "mma.sync.aligned.m16n8k8.row.col.f32.tf32.tf32.f32 "
        "{%0,%1,%2,%3}, {%4,%5,%6,%7}, {%8,%9}, {%0,%1,%2,%3};\n"
        : "+f"(d[0]), "+f"(d[1]), "+f"(d[2]), "+f"(d[3])
        : "r"(a[0]), "r"(a[1]), "r"(a[2]), "r"(a[3]), "r"(b[0]), "r"(b[1]));
}
__device__ __forceinline__ void mma_f16(float* d, const unsigned* a, const unsigned* b) {
    asm volatile(
        "mma.sync.aligned.m16n8k16.row.col.f32.f16.f16.f32 "
        "{%0,%1,%2,%3}, {%4,%5,%6,%7}, {%8,%9}, {%0,%1,%2,%3};\n"
        : "+f"(d[0]), "+f"(d[1]), "+f"(d[2]), "+f"(d[3])
        : "r"(a[0]), "r"(a[1]), "r"(a[2]), "r"(a[3]), "r"(b[0]), "r"(b[1]));
}
__device__ __forceinline__ void cp4(unsigned dst, const void* src, int sz) {
    asm volatile("cp.async.ca.shared.global [%0], [%1], 4, %2;" :: "r"(dst), "l"(src), "r"(sz));
}
__device__ __forceinline__ void cp16(unsigned dst, const void* src) {
    asm volatile("cp.async.cg.shared.global [%0], [%1], 16;" :: "r"(dst), "l"(src));
}

// ---------------- conv weight prep: fp16 tiles -------------------------------
// layout: [cc][ocb] blocks of 9216 halves: row = kp*9+tap (72), entry = n*2+lo (128),
// value = w[o = ocb*64+n][ic = cc*16 + 2*kp + lo][tap]
template<int PH>
__global__ void wprep_kernel(const float* __restrict__ w) {
    constexpr int IC = (PH == 0) ? kC : kHid;
    constexpr int OC = (PH == 0) ? kHid : kC;
    constexpr int OCB = OC / 64;
    constexpr int TOT = (IC / 16) * OCB * 9216;
    __half* dst = (PH == 0) ? g_wf1 : g_wf2;
    int i = blockIdx.x * 256 + threadIdx.x;
    if (i >= TOT) return;
    int blk = i / 9216, rem = i - blk * 9216;
    int cc = blk / OCB, ocb = blk - cc * OCB;
    int row = rem >> 7, e = rem & 127;
    int kp = row / 9, tap = row - kp * 9;
    int n = e >> 1, lo = e & 1;
    int o = ocb * 64 + n, ic = cc * 16 + kp * 2 + lo;
    dst[i] = __float2half(w[((size_t)o * IC + ic) * 9 + tap]);
}

// ---------------- LayerNorm; MODE 0: x -> g_xw (roll+window, fp32) -----------
// ----------------            MODE 1: g_x1 -> g_h0 (NHWC fp16) ----------------
template<int MODE>
__global__ void ln_kernel(const float* __restrict__ xin,
                          const float* __restrict__ gam,
                          const float* __restrict__ bet) {
    int p = blockIdx.x * 256 + threadIdx.x;
    if (p >= kNT) return;
    const float* src = (MODE == 0) ? xin : g_x1;
    int b = p / kHWp;
    int rem = p - b * kHWp;
    int hp = rem / kW, wp = rem - (rem / kW) * kW;
    int h = hp, w = wp;
    if (MODE == 0) {
        h = hp + kShift; if (h >= kH) h -= kH;
        w = wp + kShift; if (w >= kW) w -= kW;
    }
    const float* xp = src + ((size_t)b * kC) * kHWp + h * kW + w;
    float s = 0.f, s2 = 0.f;
#pragma unroll 4
    for (int c = 0; c < kC; c++) { float v = xp[(size_t)c * kHWp]; s += v; s2 += v * v; }
    float m = s * (1.f / kC);
    float var = s2 * (1.f / kC) - m * m;
    float rs = rsqrtf(var + 1e-5f);
    if (MODE == 0) {
        int win = b * 64 + (hp / 7) * 8 + (wp / 7);
        int tok = (hp % 7) * 7 + (wp % 7);
        float* op = g_xw + ((size_t)win * kTok + tok) * kC;
#pragma unroll 4
        for (int c = 0; c < kC; c++)
            op[c] = (xp[(size_t)c * kHWp] - m) * rs * gam[c] + bet[c];
    } else {
        __half* op = g_h0 + ((size_t)(b * kH + h) * kW + w) * kC;
#pragma unroll 4
        for (int c = 0; c < kC; c++) {
            float v = (xp[(size_t)c * kHWp] - m) * rs * gam[c] + bet[c];
            op[c] = __float2half(v);
        }
    }
}

// ---------------- GEMM via tf32 MMA (unchanged from R4 winner) ---------------
template<int EPI>
__global__ __launch_bounds__(128, 2) void gemm_mma_kernel(const float* __restrict__ Wm,
                                                          const float* __restrict__ bias,
                                                          const float* __restrict__ xin) {
    __shared__ unsigned sA[16][264];
    __shared__ unsigned sW[16][72];
    const float* A = (EPI == 0) ? g_xw : g_ao;
    const int tid = threadIdx.x;
    const int warp = tid >> 5, lane = tid & 31;
    const int g = lane >> 2, t = lane & 3;
    const int wm = warp;
    const int tokbase = blockIdx.x * 256;
    const int ob = blockIdx.y * 64;

    float acc[4][8][4];
#pragma unroll
    for (int i = 0; i < 4; i++)
#pragma unroll
        for (int j = 0; j < 8; j++)
#pragma unroll
            for (int k = 0; k < 4; k++) acc[i][j][k] = 0.f;

    for (int k0 = 0; k0 < kC; k0 += 16) {
        __syncthreads();
#pragma unroll
        for (int i = tid; i < 1024; i += 128) {
            int tl = i >> 2, kq = (i & 3) << 2;
            float4 v = *(const float4*)(A + (size_t)(tokbase + tl) * kC + k0 + kq);
            sA[kq + 0][tl] = f2tf32(v.x);
            sA[kq + 1][tl] = f2tf32(v.y);
            sA[kq + 2][tl] = f2tf32(v.z);
            sA[kq + 3][tl] = f2tf32(v.w);
        }
#pragma unroll
        for (int i = tid; i < 256; i += 128) {
            int n = i >> 2, kq = (i & 3) << 2;
            float4 v = *(const float4*)(Wm + (size_t)(ob + n) * kC + k0 + kq);
            sW[kq + 0][n] = f2tf32(v.x);
            sW[kq + 1][n] = f2tf32(v.y);
            sW[kq + 2][n] = f2tf32(v.z);
            sW[kq + 3][n] = f2tf32(v.w);
        }
        __syncthreads();
#pragma unroll
        for (int s = 0; s < 2; s++) {
            unsigned afr[4][4];
#pragma unroll
            for (int mf = 0; mf < 4; mf++) {
                const int mbase = wm * 64 + mf * 16;
                afr[mf][0] = sA[s * 8 + t    ][mbase + g];
                afr[mf][1] = sA[s * 8 + t    ][mbase + g + 8];
                afr[mf][2] = sA[s * 8 + t + 4][mbase + g];
                afr[mf][3] = sA[s * 8 + t + 4][mbase + g + 8];
            }
            unsigned bfr[8][2];
#pragma unroll
            for (int nf = 0; nf < 8; nf++) {
                bfr[nf][0] = sW[s * 8 + t    ][nf * 8 + g];
                bfr[nf][1] = sW[s * 8 + t + 4][nf * 8 + g];
            }
#pragma unroll
            for (int mf = 0; mf < 4; mf++)
#pragma unroll
                for (int nf = 0; nf < 8; nf++)
                    mma_tf32(acc[mf][nf], afr[mf], bfr[nf]);
        }
    }

#pragma unroll
    for (int mf = 0; mf < 4; mf++) {
        const int tk0 = tokbase + wm * 64 + mf * 16 + g;
#pragma unroll
        for (int nf = 0; nf < 8; nf++) {
            const int o0 = ob + nf * 8 + 2 * t;
            const float bv0 = bias[o0], bv1 = bias[o0 + 1];
            float vals[4] = {acc[mf][nf][0] + bv0, acc[mf][nf][1] + bv1,
                             acc[mf][nf][2] + bv0, acc[mf][nf][3] + bv1};
#pragma unroll
            for (int q = 0; q < 4; q++) {
                const int n_tok = tk0 + (q >> 1) * 8;
                const int mo = o0 + (q & 1);
                const int win = n_tok / 49, tok = n_tok - win * 49;
                if (EPI == 0) {
                    int sec = mo / kC;
                    int c = mo - sec * kC;
                    float* dst = (sec == 0) ? g_q : (sec == 1) ? g_kk : g_vv;
                    dst[((size_t)(win * kHeads + (c >> 5)) * kTok + tok) * kD + (c & 31)] = vals[q];
                } else {
                    int bb  = win >> 6;
                    int whh = (win >> 3) & 7;
                    int www = win & 7;
                    int ti = tok / 7, tj = tok - ti * 7;
                    int hi = whh * 7 + ti + kShift; if (hi >= kH) hi -= kH;
                    int wi = www * 7 + tj + kShift; if (wi >= kW) wi -= kW;
                    size_t idx = ((size_t)(bb * kC + mo) * kH + hi) * kW + wi;
                    g_x1[idx] = xin[idx] + vals[q];
                }
            }
        }
    }
}

// ---------------- attention (unchanged) --------------------------------------
__global__ __launch_bounds__(64) void attn_kernel() {
    const int wh = blockIdx.x;
    __shared__ float sq[kTok * 33], sk[kTok * kD], sv[kTok * kD];
    const size_t base = (size_t)wh * kTok * kD;
    for (int i = threadIdx.x; i < kTok * kD; i += 64) {
        int r = i >> 5, d = i & 31;
        sq[r * 33 + d] = g_q[base + i];
        sk[i] = g_kk[base + i];
        sv[i] = g_vv[base + i];
    }
    __syncthreads();
    const int r = threadIdx.x;
    if (r < kTok) {
        float qr[kD];
#pragma unroll
        for (int d = 0; d < kD; d++) qr[d] = sq[r * 33 + d];
        float p[kTok];
        float mx = -1e30f;
#pragma unroll
        for (int m = 0; m < kTok; m++) {
            float dot = 0.f;
#pragma unroll
            for (int d = 0; d < kD; d++) dot += qr[d] * sk[m * kD + d];
            dot *= 0.17677669529663689f;
            p[m] = dot;
            mx = fmaxf(mx, dot);
        }
        float sum = 0.f;
#pragma unroll
        for (int m = 0; m < kTok; m++) { p[m] = __expf(p[m] - mx); sum += p[m]; }
        const float inv = 1.f / sum;
        const int win = wh / kHeads, head = wh - win * kHeads;
        float* op = g_ao + ((size_t)win * kTok + r) * kC + head * kD;
#pragma unroll 4
        for (int d = 0; d < kD; d++) {
            float a = 0.f;
#pragma unroll
            for (int m = 0; m < kTok; m++) a += p[m] * sv[m * kD + d];
            op[d] = a * inv;
        }
    }
}

// ---------------- 3x3 conv via fp16 m16n8k16 MMA -----------------------------
// 128 thr / 4 warps, tile 8 rows x 32 cols (256 px) x 64 oc, chunk = 16 ch.
// Buffer = patch 8ch2 x10x36 (2880 w, half2 cells) + B 72 rows x 72 w (5184 w)
// = 8064 words; double-buffered cp.async (R4 skeleton).
template<int PH>
__global__ __launch_bounds__(128, 2) void conv3x3_f16_kernel(const float* __restrict__ bias,
                                                             float* __restrict__ outp) {
    constexpr int IC = (PH == 0) ? kC : kHid;
    constexpr int OC = (PH == 0) ? kHid : kC;
    constexpr int OCB = OC / 64;
    constexpr int NCH = IC / 16;
    const __half* in = (PH == 0) ? g_h0 : g_h1;
    const __half* wt = (PH == 0) ? g_wf1 : g_wf2;

    const int b = blockIdx.z;
    const int ocb = blockIdx.y;
    const int ob = ocb * 64;
    const int rt = blockIdx.x >> 1, ct = blockIdx.x & 1;
    const int r0 = rt * 8, c0col = ct * 32;

    const int tid = threadIdx.x;
    const int warp = tid >> 5, lane = tid & 31;
    const int g = lane >> 2, t = lane & 3;
    const int wm = warp;

    extern __shared__ unsigned smemd[];
    const unsigned smem0 = (unsigned)__cvta_generic_to_shared(smemd);

    auto stage = [&](int ci, int bufi) {
        const unsigned sxb = smem0 + (unsigned)(bufi * 8064 * 4);
        // patch: 340 cells (10y x 34x) x 8 half2 (16 ch); coalesced: j fastest
        for (int i = tid; i < 2720; i += 128) {
            int cell = i >> 3, j = i & 7;
            int y = cell / 34, x = cell - y * 34;
            int gy = r0 + y - 1, gx = c0col + x - 1;
            bool ok = (gy >= 0 && gy < kH && gx >= 0 && gx < kW);
            const __half* src = in + ((size_t)((b * kH + (ok ? gy : 0)) * kW + (ok ? gx : 0))) * IC
                                   + ci * 16 + j * 2;
            cp4(sxb + (unsigned)(((j * 10 + y) * 36 + x) << 2), src, ok ? 4 : 0);
        }
        // B: 72 rows x 64 half2, row-padded to 72 words in smem
        const __half* wp = wt + (size_t)(ci * OCB + ocb) * 9216;
        const unsigned swb = sxb + 2880 * 4;
        for (int i = tid; i < 1152; i += 128) {
            int r = i >> 4, q = i & 15;
            cp16(swb + (unsigned)((r * 72 + q * 4) << 2), wp + r * 128 + q * 8);
        }
        asm volatile("cp.async.commit_group;");
    };

    float acc[4][8][4];
#pragma unroll
    for (int i = 0; i < 4; i++)
#pragma unroll
        for (int j = 0; j < 8; j++)
#pragma unroll
            for (int k = 0; k < 4; k++) acc[i][j][k] = 0.f;

    stage(0, 0);

    for (int ci = 0; ci < NCH; ci++) {
        if (ci + 1 < NCH) {
            stage(ci + 1, (ci + 1) & 1);
            asm volatile("cp.async.wait_group 1;");
        } else {
            asm volatile("cp.async.wait_group 0;");
        }
        __syncthreads();
        const unsigned* buf = smemd + (ci & 1) * 8064;
#pragma unroll
        for (int dy = 0; dy < 3; dy++) {
#pragma unroll
            for (int dx = 0; dx < 3; dx++) {
                const int tap = dy * 3 + dx;
                unsigned afr[4][4];
#pragma unroll
                for (int mf = 0; mf < 4; mf++) {
                    const int ys = wm * 2 + (mf >> 1) + dy;
                    const int xb = (mf & 1) * 16 + g + dx;
                    afr[mf][0] = buf[(t * 10 + ys) * 36 + xb];        // m=g,   k=2t..2t+1
                    afr[mf][1] = buf[(t * 10 + ys) * 36 + xb + 8];    // m=g+8, k=2t..2t+1
                    afr[mf][2] = buf[((t + 4) * 10 + ys) * 36 + xb];      // m=g,   k=2t+8..9
                    afr[mf][3] = buf[((t + 4) * 10 + ys) * 36 + xb + 8];  // m=g+8, k=2t+8..9
                }
                unsigned bfr[8][2];
#pragma unroll
                for (int nf = 0; nf < 8; nf++) {
                    bfr[nf][0] = buf[2880 + (t * 9 + tap) * 72 + nf * 8 + g];
                    bfr[nf][1] = buf[2880 + ((t + 4) * 9 + tap) * 72 + nf * 8 + g];
                }
#pragma unroll
                for (int mf = 0; mf < 4; mf++)
#pragma unroll
                    for (int nf = 0; nf < 8; nf++)
                        mma_f16(acc[mf][nf], afr[mf], bfr[nf]);
            }
        }
        __syncthreads();
    }

    // epilogue
#pragma unroll
    for (int mf = 0; mf < 4; mf++) {
        const int gy = r0 + wm * 2 + (mf >> 1);
        const int gxA = c0col + (mf & 1) * 16 + g;
        const int gxB = gxA + 8;
        const bool okA = gxA < kW, okB = gxB < kW;
#pragma unroll
        for (int nf = 0; nf < 8; nf++) {
            const int o = ob + nf * 8 + 2 * t;
            const float bv0 = bias[o], bv1 = bias[o + 1];
            float v00 = acc[mf][nf][0] + bv0;
            float v01 = acc[mf][nf][1] + bv1;
            float v10 = acc[mf][nf][2] + bv0;
            float v11 = acc[mf][nf][3] + bv1;
            if (PH == 0) {
                if (okA) {
                    __half* op = g_h1 + ((size_t)(b * kH + gy) * kW + gxA) * kHid + o;
                    op[0] = __float2half(0.5f * v00 * (1.f + erff(v00 * 0.70710678118654752f)));
                    op[1] = __float2half(0.5f * v01 * (1.f + erff(v01 * 0.70710678118654752f)));
                }
                if (okB) {
                    __half* op = g_h1 + ((size_t)(b * kH + gy) * kW + gxB) * kHid + o;
                    op[0] = __float2half(0.5f * v10 * (1.f + erff(v10 * 0.70710678118654752f)));
                    op[1] = __float2half(0.5f * v11 * (1.f + erff(v11 * 0.70710678118654752f)));
                }
            } else {
                const size_t base0 = ((size_t)(b * OC + o) * kH + gy) * kW;
                const size_t base1 = ((size_t)(b * OC + o + 1) * kH + gy) * kW;
                if (okA) {
                    outp[base0 + gxA] = v00 + g_x1[base0 + gxA];
                    outp[base1 + gxA] = v01 + g_x1[base1 + gxA];
                }
                if (okB) {
                    outp[base0 + gxB] = v10 + g_x1[base0 + gxB];
                    outp[base1 + gxB] = v11 + g_x1[base1 + gxB];
                }
            }
        }
    }
}

// ---------------- launch -----------------------------------------------------
extern "C" void kernel_launch(void* const* d_in, const int* in_sizes, int n_in,
                              void* d_out, int out_size) {
    (void)in_sizes; (void)n_in; (void)out_size;
    const float* x       = (const float*)d_in[0];
    const float* ln1_g   = (const float*)d_in[1];
    const float* ln1_b   = (const float*)d_in[2];
    const float* qkv_w   = (const float*)d_in[3];
    const float* qkv_b   = (const float*)d_in[4];
    const float* proj_w  = (const float*)d_in[5];
    const float* proj_b  = (const float*)d_in[6];
    const float* ln2_g   = (const float*)d_in[7];
    const float* ln2_b   = (const float*)d_in[8];
    const float* conv1_w = (const float*)d_in[9];
    const float* conv1_b = (const float*)d_in[10];
    const float* conv2_w = (const float*)d_in[11];
    const float* conv2_b = (const float*)d_in[12];
    float* out = (float*)d_out;

    constexpr int kConvSmem = 2 * 8064 * 4;   // 64512 B
    static bool attr_done = false;
    if (!attr_done) {
        cudaFuncSetAttribute(conv3x3_f16_kernel<0>, cudaFuncAttributeMaxDynamicSharedMemorySize, kConvSmem);
        cudaFuncSetAttribute(conv3x3_f16_kernel<1>, cudaFuncAttributeMaxDynamicSharedMemorySize, kConvSmem);
        attr_done = true;
    }

    wprep_kernel<0><<<(1327104 + 255) / 256, 256>>>(conv1_w);
    wprep_kernel<1><<<(1327104 + 255) / 256, 256>>>(conv2_w);

    ln_kernel<0><<<kNT / 256, 256>>>(x, ln1_g, ln1_b);
    gemm_mma_kernel<0><<<dim3(kNT / 256, 9), 128>>>(qkv_w, qkv_b, nullptr);
    attn_kernel<<<kNWin * kHeads, 64>>>();
    gemm_mma_kernel<1><<<dim3(kNT / 256, 3), 128>>>(proj_w, proj_b, x);
    ln_kernel<1><<<kNT / 256, 256>>>(nullptr, ln2_g, ln2_b);
    conv3x3_f16_kernel<0><<<dim3(14, 12, kB), 128, kConvSmem>>>(conv1_b, nullptr);
    conv3x3_f16_kernel<1><<<dim3(14, 3, kB), 128, kConvSmem>>>(conv2_b, out);
}

// round 10
// speedup vs baseline: 2.2083x; 1.0120x over previous
#include <cuda_runtime.h>
#include <cuda_fp16.h>
#include <math.h>

namespace {
constexpr int kB = 32, kC = 192, kH = 56, kW = 56;
constexpr int kHeads = 6, kD = 32, kWS = 7, kShift = 3, kHid = 768;
constexpr int kNWin = kB * 8 * 8;   // 2048 windows
constexpr int kTok = kWS * kWS;     // 49
constexpr int kNT = kNWin * kTok;   // 100352 tokens
constexpr int kHWp = kH * kW;       // 3136
}

// ---------------- scratch (static __device__, allocation-free) ----------------
__device__ __half g_wf1[1327104];               // conv1 w fp16 tiles [cc][ocb][72][128]
__device__ __half g_wf2[1327104];               // conv2 w fp16 tiles
__device__ __half g_wq[3 * kC * kC];            // qkv w fp16 tiles [nb][cc][kp][128]
__device__ __half g_wp[kC * kC];                // proj w fp16 tiles
__device__ __half g_xw[(size_t)kNT * kC];       // LN1 out fp16, [win][tok][c]
__device__ float g_q [(size_t)kNT * kC];
__device__ float g_kk[(size_t)kNT * kC];
__device__ float g_vv[(size_t)kNT * kC];
__device__ __half g_ao[(size_t)kNT * kC];       // attn out fp16, [win][tok][c]
__device__ float g_x1[(size_t)kNT * kC];        // x + attn branch (NCHW)
__device__ __half g_h0[(size_t)kNT * kC];       // LN2 out, NHWC fp16
__device__ __half g_h1[(size_t)kNT * kHid];     // conv1+gelu out, NHWC fp16

// ---------------- helpers ----------------------------------------------------
__device__ __forceinline__ void mma_f16(float* d, const unsigned* a, const unsigned* b) {
    asm volatile(
        "mma.sync.aligned.m16n8k16.row.col.f32.f16.f16.f32 "
        "{%0,%1,%2,%3}, {%4,%5,%6,%7}, {%8,%9}, {%0,%1,%2,%3};\n"
        : "+f"(d[0]), "+f"(d[1]), "+f"(d[2]), "+f"(d[3])
        : "r"(a[0]), "r"(a[1]), "r"(a[2]), "r"(a[3]), "r"(b[0]), "r"(b[1]));
}
__device__ __forceinline__ void cp4(unsigned dst, const void* src, int sz) {
    asm volatile("cp.async.ca.shared.global [%0], [%1], 4, %2;" :: "r"(dst), "l"(src), "r"(sz));
}
__device__ __forceinline__ void cp16(unsigned dst, const void* src) {
    asm volatile("cp.async.cg.shared.global [%0], [%1], 16;" :: "r"(dst), "l"(src));
}

// ---------------- conv weight prep (unchanged from R9) -----------------------
template<int PH>
__global__ void wprep_kernel(const float* __restrict__ w) {
    constexpr int IC = (PH == 0) ? kC : kHid;
    constexpr int OC = (PH == 0) ? kHid : kC;
    constexpr int OCB = OC / 64;
    constexpr int TOT = (IC / 16) * OCB * 9216;
    __half* dst = (PH == 0) ? g_wf1 : g_wf2;
    int i = blockIdx.x * 256 + threadIdx.x;
    if (i >= TOT) return;
    int blk = i / 9216, rem = i - blk * 9216;
    int cc = blk / OCB, ocb = blk - cc * OCB;
    int row = rem >> 7, e = rem & 127;
    int kp = row / 9, tap = row - kp * 9;
    int n = e >> 1, lo = e & 1;
    int o = ocb * 64 + n, ic = cc * 16 + kp * 2 + lo;
    dst[i] = __float2half(w[((size_t)o * IC + ic) * 9 + tap]);
}

// ---------------- gemm weight prep: [nb][cc][kp][n*2+lo] fp16 ----------------
// value = w[nb*64+n][cc*16+2kp+lo];  block = nb*12+cc, 1024 halves per block.
template<int P>
__global__ void wprep_gemm_kernel(const float* __restrict__ w) {
    constexpr int NB = (P == 0) ? 9 : 3;
    constexpr int TOT = NB * 12 * 1024;
    __half* dst = (P == 0) ? g_wq : g_wp;
    int i = blockIdx.x * 256 + threadIdx.x;
    if (i >= TOT) return;
    int blk = i >> 10, rem = i & 1023;
    int nb = blk / 12, cc = blk - nb * 12;
    int kp = rem >> 7, e = rem & 127;
    int n = e >> 1, lo = e & 1;
    dst[i] = __float2half(w[(size_t)(nb * 64 + n) * kC + cc * 16 + kp * 2 + lo]);
}

// ---------------- LayerNorm; MODE 0: x -> g_xw fp16 (roll+window) ------------
// ----------------            MODE 1: g_x1 -> g_h0 (NHWC fp16) ----------------
template<int MODE>
__global__ void ln_kernel(const float* __restrict__ xin,
                          const float* __restrict__ gam,
                          const float* __restrict__ bet) {
    int p = blockIdx.x * 256 + threadIdx.x;
    if (p >= kNT) return;
    const float* src = (MODE == 0) ? xin : g_x1;
    int b = p / kHWp;
    int rem = p - b * kHWp;
    int hp = rem / kW, wp = rem - (rem / kW) * kW;
    int h = hp, w = wp;
    if (MODE == 0) {
        h = hp + kShift; if (h >= kH) h -= kH;
        w = wp + kShift; if (w >= kW) w -= kW;
    }
    const float* xp = src + ((size_t)b * kC) * kHWp + h * kW + w;
    float s = 0.f, s2 = 0.f;
#pragma unroll 4
    for (int c = 0; c < kC; c++) { float v = xp[(size_t)c * kHWp]; s += v; s2 += v * v; }
    float m = s * (1.f / kC);
    float var = s2 * (1.f / kC) - m * m;
    float rs = rsqrtf(var + 1e-5f);
    if (MODE == 0) {
        int win = b * 64 + (hp / 7) * 8 + (wp / 7);
        int tok = (hp % 7) * 7 + (wp % 7);
        __half* op = g_xw + ((size_t)win * kTok + tok) * kC;
#pragma unroll 4
        for (int c = 0; c < kC; c++) {
            float v = (xp[(size_t)c * kHWp] - m) * rs * gam[c] + bet[c];
            op[c] = __float2half(v);
        }
    } else {
        __half* op = g_h0 + ((size_t)(b * kH + h) * kW + w) * kC;
#pragma unroll 4
        for (int c = 0; c < kC; c++) {
            float v = (xp[(size_t)c * kHWp] - m) * rs * gam[c] + bet[c];
            op[c] = __float2half(v);
        }
    }
}

// ---------------- GEMM via fp16 m16n8k16: 128 thr, warp = 64 tok x 64 out ----
// Block tile 256 tok x 64 out, k-chunk 16 (one k16 MMA per frag pair).
// EPI 0: A=g_xw -> q/k/v fp32.  EPI 1: A=g_ao -> inverse-roll + resid fp32.
template<int EPI>
__global__ __launch_bounds__(128, 2) void gemm_f16_kernel(const float* __restrict__ bias,
                                                          const float* __restrict__ xin) {
    __shared__ unsigned sA[8][264];   // [kp][tok] half2; 264 % 32 == 8 -> conflict-free
    __shared__ unsigned sW[8][72];    // [kp][n] half2
    const __half* A = (EPI == 0) ? g_xw : g_ao;
    const __half* Wg = (EPI == 0) ? g_wq : g_wp;
    const int tid = threadIdx.x;
    const int warp = tid >> 5, lane = tid & 31;
    const int g = lane >> 2, t = lane & 3;
    const int wm = warp;
    const int tokbase = blockIdx.x * 256;
    const int nb = blockIdx.y;
    const int ob = nb * 64;

    float acc[4][8][4];
#pragma unroll
    for (int i = 0; i < 4; i++)
#pragma unroll
        for (int j = 0; j < 8; j++)
#pragma unroll
            for (int k = 0; k < 4; k++) acc[i][j][k] = 0.f;

    const int wkp = tid >> 4, wq = tid & 15;
    for (int cc = 0; cc < 12; cc++) {
        __syncthreads();
        // A: 256 tok x 8 half2-kp; tok = s*128 + tid (stride-1 STS, conflict-free)
#pragma unroll
        for (int s = 0; s < 2; s++) {
            const int tok = s * 128 + tid;
            const uint4* ap = (const uint4*)(A + (size_t)(tokbase + tok) * kC + cc * 16);
            uint4 v0 = ap[0], v1 = ap[1];
            sA[0][tok] = v0.x; sA[1][tok] = v0.y; sA[2][tok] = v0.z; sA[3][tok] = v0.w;
            sA[4][tok] = v1.x; sA[5][tok] = v1.y; sA[6][tok] = v1.z; sA[7][tok] = v1.w;
        }
        // W: straight copy of pre-packed tile (1024 halves)
        {
            const uint4 v = *(const uint4*)(Wg + (size_t)(nb * 12 + cc) * 1024 + wkp * 128 + wq * 8);
            *(uint4*)&sW[wkp][wq * 4] = v;
        }
        __syncthreads();
        unsigned afr[4][4];
#pragma unroll
        for (int mf = 0; mf < 4; mf++) {
            const int mbase = wm * 64 + mf * 16;
            afr[mf][0] = sA[t    ][mbase + g];
            afr[mf][1] = sA[t    ][mbase + g + 8];
            afr[mf][2] = sA[t + 4][mbase + g];
            afr[mf][3] = sA[t + 4][mbase + g + 8];
        }
        unsigned bfr[8][2];
#pragma unroll
        for (int nf = 0; nf < 8; nf++) {
            bfr[nf][0] = sW[t    ][nf * 8 + g];
            bfr[nf][1] = sW[t + 4][nf * 8 + g];
        }
#pragma unroll
        for (int mf = 0; mf < 4; mf++)
#pragma unroll
            for (int nf = 0; nf < 8; nf++)
                mma_f16(acc[mf][nf], afr[mf], bfr[nf]);
    }

#pragma unroll
    for (int mf = 0; mf < 4; mf++) {
        const int tk0 = tokbase + wm * 64 + mf * 16 + g;
#pragma unroll
        for (int nf = 0; nf < 8; nf++) {
            const int o0 = ob + nf * 8 + 2 * t;
            const float bv0 = bias[o0], bv1 = bias[o0 + 1];
            float vals[4] = {acc[mf][nf][0] + bv0, acc[mf][nf][1] + bv1,
                             acc[mf][nf][2] + bv0, acc[mf][nf][3] + bv1};
#pragma unroll
            for (int q = 0; q < 4; q++) {
                const int n_tok = tk0 + (q >> 1) * 8;
                const int mo = o0 + (q & 1);
                const int win = n_tok / 49, tok = n_tok - win * 49;
                if (EPI == 0) {
                    int sec = mo / kC;
                    int c = mo - sec * kC;
                    float* dst = (sec == 0) ? g_q : (sec == 1) ? g_kk : g_vv;
                    dst[((size_t)(win * kHeads + (c >> 5)) * kTok + tok) * kD + (c & 31)] = vals[q];
                } else {
                    int bb  = win >> 6;
                    int whh = (win >> 3) & 7;
                    int www = win & 7;
                    int ti = tok / 7, tj = tok - ti * 7;
                    int hi = whh * 7 + ti + kShift; if (hi >= kH) hi -= kH;
                    int wi = www * 7 + tj + kShift; if (wi >= kW) wi -= kW;
                    size_t idx = ((size_t)(bb * kC + mo) * kH + hi) * kW + wi;
                    g_x1[idx] = xin[idx] + vals[q];
                }
            }
        }
    }
}

// ---------------- attention (writes fp16 g_ao) --------------------------------
__global__ __launch_bounds__(64) void attn_kernel() {
    const int wh = blockIdx.x;
    __shared__ float sq[kTok * 33], sk[kTok * kD], sv[kTok * kD];
    const size_t base = (size_t)wh * kTok * kD;
    for (int i = threadIdx.x; i < kTok * kD; i += 64) {
        int r = i >> 5, d = i & 31;
        sq[r * 33 + d] = g_q[base + i];
        sk[i] = g_kk[base + i];
        sv[i] = g_vv[base + i];
    }
    __syncthreads();
    const int r = threadIdx.x;
    if (r < kTok) {
        float qr[kD];
#pragma unroll
        for (int d = 0; d < kD; d++) qr[d] = sq[r * 33 + d];
        float p[kTok];
        float mx = -1e30f;
#pragma unroll
        for (int m = 0; m < kTok; m++) {
            float dot = 0.f;
#pragma unroll
            for (int d = 0; d < kD; d++) dot += qr[d] * sk[m * kD + d];
            dot *= 0.17677669529663689f;
            p[m] = dot;
            mx = fmaxf(mx, dot);
        }
        float sum = 0.f;
#pragma unroll
        for (int m = 0; m < kTok; m++) { p[m] = __expf(p[m] - mx); sum += p[m]; }
        const float inv = 1.f / sum;
        const int win = wh / kHeads, head = wh - win * kHeads;
        __half* op = g_ao + ((size_t)win * kTok + r) * kC + head * kD;
#pragma unroll 4
        for (int d = 0; d < kD; d++) {
            float a = 0.f;
#pragma unroll
            for (int m = 0; m < kTok; m++) a += p[m] * sv[m * kD + d];
            op[d] = __float2half(a * inv);
        }
    }
}

// ---------------- 3x3 conv via fp16 m16n8k16 MMA (unchanged from R9) ---------
template<int PH>
__global__ __launch_bounds__(128, 2) void conv3x3_f16_kernel(const float* __restrict__ bias,
                                                             float* __restrict__ outp) {
    constexpr int IC = (PH == 0) ? kC : kHid;
    constexpr int OC = (PH == 0) ? kHid : kC;
    constexpr int OCB = OC / 64;
    constexpr int NCH = IC / 16;
    const __half* in = (PH == 0) ? g_h0 : g_h1;
    const __half* wt = (PH == 0) ? g_wf1 : g_wf2;

    const int b = blockIdx.z;
    const int ocb = blockIdx.y;
    const int ob = ocb * 64;
    const int rt = blockIdx.x >> 1, ct = blockIdx.x & 1;
    const int r0 = rt * 8, c0col = ct * 32;

    const int tid = threadIdx.x;
    const int warp = tid >> 5, lane = tid & 31;
    const int g = lane >> 2, t = lane & 3;
    const int wm = warp;

    extern __shared__ unsigned smemd[];
    const unsigned smem0 = (unsigned)__cvta_generic_to_shared(smemd);

    auto stage = [&](int ci, int bufi) {
        const unsigned sxb = smem0 + (unsigned)(bufi * 8064 * 4);
        for (int i = tid; i < 2720; i += 128) {
            int cell = i >> 3, j = i & 7;
            int y = cell / 34, x = cell - y * 34;
            int gy = r0 + y - 1, gx = c0col + x - 1;
            bool ok = (gy >= 0 && gy < kH && gx >= 0 && gx < kW);
            const __half* src = in + ((size_t)((b * kH + (ok ? gy : 0)) * kW + (ok ? gx : 0))) * IC
                                   + ci * 16 + j * 2;
            cp4(sxb + (unsigned)(((j * 10 + y) * 36 + x) << 2), src, ok ? 4 : 0);
        }
        const __half* wp = wt + (size_t)(ci * OCB + ocb) * 9216;
        const unsigned swb = sxb + 2880 * 4;
        for (int i = tid; i < 1152; i += 128) {
            int r = i >> 4, q = i & 15;
            cp16(swb + (unsigned)((r * 72 + q * 4) << 2), wp + r * 128 + q * 8);
        }
        asm volatile("cp.async.commit_group;");
    };

    float acc[4][8][4];
#pragma unroll
    for (int i = 0; i < 4; i++)
#pragma unroll
        for (int j = 0; j < 8; j++)
#pragma unroll
            for (int k = 0; k < 4; k++) acc[i][j][k] = 0.f;

    stage(0, 0);

    for (int ci = 0; ci < NCH; ci++) {
        if (ci + 1 < NCH) {
            stage(ci + 1, (ci + 1) & 1);
            asm volatile("cp.async.wait_group 1;");
        } else {
            asm volatile("cp.async.wait_group 0;");
        }
        __syncthreads();
        const unsigned* buf = smemd + (ci & 1) * 8064;
#pragma unroll
        for (int dy = 0; dy < 3; dy++) {
#pragma unroll
            for (int dx = 0; dx < 3; dx++) {
                const int tap = dy * 3 + dx;
                unsigned afr[4][4];
#pragma unroll
                for (int mf = 0; mf < 4; mf++) {
                    const int ys = wm * 2 + (mf >> 1) + dy;
                    const int xb = (mf & 1) * 16 + g + dx;
                    afr[mf][0] = buf[(t * 10 + ys) * 36 + xb];
                    afr[mf][1] = buf[(t * 10 + ys) * 36 + xb + 8];
                    afr[mf][2] = buf[((t + 4) * 10 + ys) * 36 + xb];
                    afr[mf][3] = buf[((t + 4) * 10 + ys) * 36 + xb + 8];
                }
                unsigned bfr[8][2];
#pragma unroll
                for (int nf = 0; nf < 8; nf++) {
                    bfr[nf][0] = buf[2880 + (t * 9 + tap) * 72 + nf * 8 + g];
                    bfr[nf][1] = buf[2880 + ((t + 4) * 9 + tap) * 72 + nf * 8 + g];
                }
#pragma unroll
                for (int mf = 0; mf < 4; mf++)
#pragma unroll
                    for (int nf = 0; nf < 8; nf++)
                        mma_f16(acc[mf][nf], afr[mf], bfr[nf]);
            }
        }
        __syncthreads();
    }

#pragma unroll
    for (int mf = 0; mf < 4; mf++) {
        const int gy = r0 + wm * 2 + (mf >> 1);
        const int gxA = c0col + (mf & 1) * 16 + g;
        const int gxB = gxA + 8;
        const bool okA = gxA < kW, okB = gxB < kW;
#pragma unroll
        for (int nf = 0; nf < 8; nf++) {
            const int o = ob + nf * 8 + 2 * t;
            const float bv0 = bias[o], bv1 = bias[o + 1];
            float v00 = acc[mf][nf][0] + bv0;
            float v01 = acc[mf][nf][1] + bv1;
            float v10 = acc[mf][nf][2] + bv0;
            float v11 = acc[mf][nf][3] + bv1;
            if (PH == 0) {
                if (okA) {
                    __half* op = g_h1 + ((size_t)(b * kH + gy) * kW + gxA) * kHid + o;
                    op[0] = __float2half(0.5f * v00 * (1.f + erff(v00 * 0.70710678118654752f)));
                    op[1] = __float2half(0.5f * v01 * (1.f + erff(v01 * 0.70710678118654752f)));
                }
                if (okB) {
                    __half* op = g_h1 + ((size_t)(b * kH + gy) * kW + gxB) * kHid + o;
                    op[0] = __float2half(0.5f * v10 * (1.f + erff(v10 * 0.70710678118654752f)));
                    op[1] = __float2half(0.5f * v11 * (1.f + erff(v11 * 0.70710678118654752f)));
                }
            } else {
                const size_t base0 = ((size_t)(b * OC + o) * kH + gy) * kW;
                const size_t base1 = ((size_t)(b * OC + o + 1) * kH + gy) * kW;
                if (okA) {
                    outp[base0 + gxA] = v00 + g_x1[base0 + gxA];
                    outp[base1 + gxA] = v01 + g_x1[base1 + gxA];
                }
                if (okB) {
                    outp[base0 + gxB] = v10 + g_x1[base0 + gxB];
                    outp[base1 + gxB] = v11 + g_x1[base1 + gxB];
                }
            }
        }
    }
}

// ---------------- launch -----------------------------------------------------
extern "C" void kernel_launch(void* const* d_in, const int* in_sizes, int n_in,
                              void* d_out, int out_size) {
    (void)in_sizes; (void)n_in; (void)out_size;
    const float* x       = (const float*)d_in[0];
    const float* ln1_g   = (const float*)d_in[1];
    const float* ln1_b   = (const float*)d_in[2];
    const float* qkv_w   = (const float*)d_in[3];
    const float* qkv_b   = (const float*)d_in[4];
    const float* proj_w  = (const float*)d_in[5];
    const float* proj_b  = (const float*)d_in[6];
    const float* ln2_g   = (const float*)d_in[7];
    const float* ln2_b   = (const float*)d_in[8];
    const float* conv1_w = (const float*)d_in[9];
    const float* conv1_b = (const float*)d_in[10];
    const float* conv2_w = (const float*)d_in[11];
    const float* conv2_b = (const float*)d_in[12];
    float* out = (float*)d_out;

    constexpr int kConvSmem = 2 * 8064 * 4;   // 64512 B
    static bool attr_done = false;
    if (!attr_done) {
        cudaFuncSetAttribute(conv3x3_f16_kernel<0>, cudaFuncAttributeMaxDynamicSharedMemorySize, kConvSmem);
        cudaFuncSetAttribute(conv3x3_f16_kernel<1>, cudaFuncAttributeMaxDynamicSharedMemorySize, kConvSmem);
        attr_done = true;
    }

    wprep_kernel<0><<<(1327104 + 255) / 256, 256>>>(conv1_w);
    wprep_kernel<1><<<(1327104 + 255) / 256, 256>>>(conv2_w);
    wprep_gemm_kernel<0><<<(9 * 12 * 1024 + 255) / 256, 256>>>(qkv_w);
    wprep_gemm_kernel<1><<<(3 * 12 * 1024 + 255) / 256, 256>>>(proj_w);

    ln_kernel<0><<<kNT / 256, 256>>>(x, ln1_g, ln1_b);
    gemm_f16_kernel<0><<<dim3(kNT / 256, 9), 128>>>(qkv_b, nullptr);
    attn_kernel<<<kNWin * kHeads, 64>>>();
    gemm_f16_kernel<1><<<dim3(kNT / 256, 3), 128>>>(proj_b, x);
    ln_kernel<1><<<kNT / 256, 256>>>(nullptr, ln2_g, ln2_b);
    conv3x3_f16_kernel<0><<<dim3(14, 12, kB), 128, kConvSmem>>>(conv1_b, nullptr);
    conv3x3_f16_kernel<1><<<dim3(14, 3, kB), 128, kConvSmem>>>(conv2_b, out);
}